// round 12
// baseline (speedup 1.0000x reference)
#include <cuda_runtime.h>
#include <cuda_fp16.h>
#include <cstdint>
#include <math.h>

#define NN   100000
#define EE   200000
#define PP2  250000
#define PP3  500000
#define GG   2048
#define NCC  10

// ---------------- scratch (device globals; no allocations) ----------------
__device__ float  d_W0[NN * 64];
__device__ __half d_GNODE[(size_t)NN * 256];   // fp16 gate tables
__device__ __half d_GEDGE[(size_t)EE * 256];
__device__ __half d_R0[(size_t)NN * 256];
__device__ float  d_H0[NN * 64];
__device__ __half d_C0[NN * 64];
__device__ float  d_ACC[NN * 64];
__device__ float  d_TMP[NN * 64];
__device__ float  d_W1[NN * 64];
__device__ float  d_W2[NN * 64];
__device__ float  d_WXP[256 * 64];
__device__ float  d_WHP[256 * 64];
__device__ float  d_WHHT[64 * 256];
__device__ float  d_BIASP[256];
__device__ float  d_FWX[18 * 256];
__device__ float  d_FBX[256];
__device__ float  d_FWE[18 * 256];
__device__ float  d_FBE[256];
__device__ float  d_STATS[256];   // S0=[0..127], S1=[128..255]
__device__ float  d_S[132];
__device__ float  d_POOL[GG * 64];

__device__ __forceinline__ float fsig(float x) { return 1.0f / (1.0f + __expf(-x)); }
__device__ __forceinline__ float ftanh(float x) { return 2.0f * fsig(2.0f * x) - 1.0f; }

// load 4 consecutive halfs (one gate quad) as float4
__device__ __forceinline__ float4 ldh4(const __half* base, size_t row, int k) {
    uint2 u = *reinterpret_cast<const uint2*>(base + row * 256 + 4 * k);
    __half2 p = *reinterpret_cast<__half2*>(&u.x);
    __half2 q = *reinterpret_cast<__half2*>(&u.y);
    float2 f0 = __half22float2(p), f1 = __half22float2(q);
    return make_float4(f0.x, f0.y, f1.x, f1.y);
}

// ---------------- zero ----------------
__global__ void k_zero(float* p, int n) {
    int i = blockIdx.x * blockDim.x + threadIdx.x;
    if (i < n) p[i] = 0.0f;
}

// ---------------- weight permutation ----------------
__global__ void k_prep(const float* __restrict__ wih, const float* __restrict__ whh,
                       const float* __restrict__ bih, const float* __restrict__ bhh) {
    int i = blockIdx.x * blockDim.x + threadIdx.x;
    if (i >= 256 * 64) return;
    int jp = i >> 6, m = i & 63;
    int k = jp >> 2, q = jp & 3;
    int j = q * 64 + k;
    d_WXP[i] = wih[j * 128 + m];
    d_WHP[i] = whh[j * 64 + m];
    d_WHHT[m * 256 + jp] = whh[j * 64 + m];
    if (m == 0) d_BIASP[jp] = bih[j] + bhh[j];
}

// ---------------- fused encoder->gate weights ----------------
__global__ void k_fuse(const float* __restrict__ wfeat, const float* __restrict__ bfeat,
                       const float* __restrict__ wbond, const float* __restrict__ bbond,
                       const float* __restrict__ wih, const float* __restrict__ bih,
                       const float* __restrict__ bhh) {
    int t = blockIdx.x * blockDim.x + threadIdx.x;
    if (t >= 2 * 19 * 256) return;
    int jp = t & 255;
    int f = (t >> 8) % 19;
    int mat = t / (19 * 256);
    int k = jp >> 2, q = jp & 3;
    int j = q * 64 + k;
    const float* wrow = wih + j * 128 + (mat ? 64 : 0);
    float s = 0.0f;
    if (f < 18) {
        const float* src = mat ? wbond : wfeat;
#pragma unroll 16
        for (int m = 0; m < 64; m++) s += src[f * 64 + m] * wrow[m];
        (mat ? d_FWE : d_FWX)[f * 256 + jp] = s;
    } else {
        const float* bsrc = mat ? bbond : bfeat;
#pragma unroll 16
        for (int m = 0; m < 64; m++) s += bsrc[m] * wrow[m];
        if (!mat) s += bih[j] + bhh[j];
        (mat ? d_FBE : d_FBX)[jp] = s;
    }
}

// ---------------- encoder for W0 ----------------
__global__ void k_encode(const float* __restrict__ in, const float* __restrict__ w,
                         const float* __restrict__ b, float* __restrict__ out, int R) {
    long long tid = (long long)blockIdx.x * blockDim.x + threadIdx.x;
    if (tid >= (long long)R * 64) return;
    int ch = (int)(tid & 63);
    long long r = tid >> 6;
    const float* xr = in + r * 18;
    float acc = b[ch];
#pragma unroll
    for (int j = 0; j < 18; j++) acc += xr[j] * w[j * 64 + ch];
    out[tid] = acc;
}

// ---------------- direct gate table: out[R,256] = in[R,18] @ FW + FB (half out) ------
__global__ void __launch_bounds__(256) k_direct(
        const float* __restrict__ in, const float* __restrict__ FW,
        const float* __restrict__ FB, __half* __restrict__ out, int R) {
    __shared__ float FWs[18 * 256];
    __shared__ float Fbs[256];
    __shared__ float xs[16 * 18];
    int tid = threadIdx.x;
    for (int i = tid; i < 18 * 256; i += 256) FWs[i] = FW[i];
    Fbs[tid] = FB[tid];

    long long stride = (long long)gridDim.x * 16;
    long long base = (long long)blockIdx.x * 16;
    auto ldx = [&](long long b, int i) -> float {
        int row = i / 18, col = i - row * 18;
        long long gr = b + row;
        return (i < 288 && gr < R) ? in[gr * 18 + col] : 0.0f;
    };
    float v0 = ldx(base, tid), v1 = ldx(base, tid + 256);
    __syncthreads();

    for (; base < R; base += stride) {
        xs[tid < 288 ? tid : 0] = tid < 288 ? v0 : xs[0];
        if (tid < 32) xs[tid + 256] = v1;
        __syncthreads();
        long long nb = base + stride;
        v0 = ldx(nb, tid); v1 = ldx(nb, tid + 256);
        float acc[16];
#pragma unroll
        for (int r = 0; r < 16; r++) acc[r] = Fbs[tid];
#pragma unroll
        for (int f = 0; f < 18; f++) {
            float w = FWs[f * 256 + tid];
#pragma unroll
            for (int r = 0; r < 16; r++) acc[r] += w * xs[r * 18 + f];
        }
#pragma unroll
        for (int r = 0; r < 16; r++)
            if (base + r < R) out[(base + r) * 256 + tid] = __float2half(acc[r]);
        __syncthreads();
    }
}

// ---------------- gate tables: out[R,256] = blend(in,in2)[R,64] @ W^T (+bias), half out --
__global__ void k_gtab(const float* __restrict__ in, const float* __restrict__ in2,
                       const float* __restrict__ W, const float* __restrict__ bias,
                       __half* __restrict__ out, int R) {
    extern __shared__ float sh[];
    float* Ws = sh;             // [256][64] swizzled
    float* xs = sh + 256 * 64;  // [8][64]
    int tid = threadIdx.x;
    for (int i = tid; i < 256 * 64; i += blockDim.x) {
        int jp = i >> 6, m = i & 63;
        int mg = m >> 2, mj = m & 3;
        Ws[jp * 64 + (((mg ^ (jp & 7)) << 2) | mj)] = W[i];
    }
    float bv = bias ? bias[tid] : 0.0f;

    const float4* Ws4 = (const float4*)Ws;
    const float4* xs4 = (const float4*)xs;
    int sw = tid & 7;
    int wb = tid * 16;
    long long stride = (long long)gridDim.x * 8;
    long long base = (long long)blockIdx.x * 8;

    auto ldx = [&](long long b, int i) -> float {
        int row = i >> 6, col = i & 63;
        long long gr = b + row;
        float v = 0.0f;
        if (gr < R) {
            v = in[gr * 64 + col];
            if (in2) v = 0.75f * v - 0.25f * in2[gr * 64 + col];
        }
        return v;
    };
    float v0 = ldx(base, tid), v1 = ldx(base, tid + 256);
    __syncthreads();

    for (; base < R; base += stride) {
        xs[tid] = v0;
        xs[tid + 256] = v1;
        __syncthreads();
        long long nb = base + stride;
        v0 = ldx(nb, tid);
        v1 = ldx(nb, tid + 256);
        float acc[8];
#pragma unroll
        for (int r = 0; r < 8; r++) acc[r] = bv;
#pragma unroll
        for (int mg = 0; mg < 16; mg++) {
            float4 w = Ws4[wb + (mg ^ sw)];
#pragma unroll
            for (int r = 0; r < 8; r++) {
                float4 xv = xs4[r * 16 + mg];
                acc[r] += w.x * xv.x + w.y * xv.y + w.z * xv.z + w.w * xv.w;
            }
        }
#pragma unroll
        for (int r = 0; r < 8; r++)
            if (base + r < R) out[(base + r) * 256 + tid] = __float2half(acc[r]);
        __syncthreads();
    }
}

// ---------------- per-node step-0 state from (half) gate table ----------------
__global__ void k_h0c0(const __half* __restrict__ gnode, float* __restrict__ h0,
                       __half* __restrict__ c0) {
    long long gid = (long long)blockIdx.x * blockDim.x + threadIdx.x;
    if (gid >= (long long)NN * 64) return;
    uint2 u = reinterpret_cast<const uint2*>(gnode)[gid];
    __half2 p = *reinterpret_cast<__half2*>(&u.x);
    __half2 q = *reinterpret_cast<__half2*>(&u.y);
    float2 f0 = __half22float2(p), f1 = __half22float2(q);
    float c = fsig(f0.x) * ftanh(f1.x);
    float h = fsig(f1.y) * ftanh(c);
    c0[gid] = __float2half(c);
    h0[gid] = h;
}

// ---------------- conv0: pure gather + elementwise LSTM step 1 ----------------
__global__ void k_lstm2(const int* __restrict__ paths, const int* __restrict__ ei,
                        const __half* __restrict__ gnode, const __half* __restrict__ gedge,
                        const __half* __restrict__ r0tab, const __half* __restrict__ c0tab,
                        float* __restrict__ acc, int P) {
    long long gid = (long long)blockIdx.x * blockDim.x + threadIdx.x;
    if (gid >= (long long)P * 64) return;
    int k = (int)(gid & 63);
    long long p = gid >> 6;
    int n0 = paths[p * 2], n1 = paths[p * 2 + 1], e0 = ei[p];
    float4 a = ldh4(gnode, (size_t)n1, k);
    float4 b = ldh4(gedge, (size_t)e0, k);
    float4 r = ldh4(r0tab, (size_t)n0, k);
    float c0 = __half2float(c0tab[(size_t)n0 * 64 + k]);
    float gx = a.x + b.x + r.x, gy = a.y + b.y + r.y;
    float gz = a.z + b.z + r.z, gw = a.w + b.w + r.w;
    float c1 = fsig(gy) * c0 + fsig(gx) * ftanh(gz);
    float h1 = fsig(gw) * ftanh(c1);
    atomicAdd(&acc[(size_t)n1 * 64 + k], h1);
}

// ---------------- conv1: HMMA tensor-core recurrence GEMM ----------------
// Tile = 16 paths. A = h1 [16x64] fp16 (smem, pad 72). B = WhhT [64x256] fp16,
// stationary in per-warp register fragments (warp w owns gate cols 32w..32w+31).
// D staged via smem G (pad 268), then per-thread gather/activation/atomic epilogue.
__global__ void __launch_bounds__(256) k_lstm3(
        const int* __restrict__ paths, const int* __restrict__ ei,
        const __half* __restrict__ gnode, const __half* __restrict__ gedge,
        const __half* __restrict__ r0tab, const __half* __restrict__ c0tab,
        float* __restrict__ acc, int P) {
    __shared__ __half h1sm[16 * 72];
    __shared__ float G[16 * 268];
    int tid = threadIdx.x;
    int k = tid & 63;
    int lp = tid >> 6;
    int warp = tid >> 5;
    int lane = tid & 31;
    int g = lane >> 2, t = lane & 3;

    // stationary B fragments: m16n8k16 "col" B layout
    // b0 = {B[2t][g], B[2t+1][g]}, b1 = {B[2t+8][g], B[2t+9][g]}  (B[k][n] = WhhT[k][n])
    unsigned bf[4][4][2];
#pragma unroll
    for (int kk = 0; kk < 4; kk++)
#pragma unroll
        for (int nt = 0; nt < 4; nt++) {
            int n = (warp * 4 + nt) * 8 + g;
            int k0 = kk * 16 + 2 * t;
            __half2 b0 = __floats2half2_rn(d_WHHT[k0 * 256 + n], d_WHHT[(k0 + 1) * 256 + n]);
            __half2 b1 = __floats2half2_rn(d_WHHT[(k0 + 8) * 256 + n], d_WHHT[(k0 + 9) * 256 + n]);
            bf[kk][nt][0] = *reinterpret_cast<unsigned*>(&b0);
            bf[kk][nt][1] = *reinterpret_cast<unsigned*>(&b1);
        }

    for (long long base = (long long)blockIdx.x * 16; base < P; base += (long long)gridDim.x * 16) {
        float4 r[4];
        float c1v[4];
        int n2r[4];
#pragma unroll
        for (int i = 0; i < 4; i++) {
            long long p = base + lp + 4 * i;
            bool valid = p < P;
            long long pi = valid ? p : 0;
            int n0 = paths[pi * 3], n1 = paths[pi * 3 + 1], n2 = paths[pi * 3 + 2];
            int e0 = ei[pi * 2], e1 = ei[pi * 2 + 1];
            n2r[i] = valid ? n2 : -1;
            // step-1 gathers + activation
            float4 a = ldh4(gnode, (size_t)n1, k);
            float4 b = ldh4(gedge, (size_t)e0, k);
            float4 rr = ldh4(r0tab, (size_t)n0, k);
            float c0 = __half2float(c0tab[(size_t)n0 * 64 + k]);
            float gx = a.x + b.x + rr.x, gy = a.y + b.y + rr.y;
            float gz = a.z + b.z + rr.z, gw = a.w + b.w + rr.w;
            float c = fsig(gy) * c0 + fsig(gx) * ftanh(gz);
            c1v[i] = c;
            h1sm[(lp + 4 * i) * 72 + k] = __float2half(fsig(gw) * ftanh(c));
            // step-2 gate base
            float4 a2 = ldh4(gnode, (size_t)n2, k);
            float4 b2 = ldh4(gedge, (size_t)e1, k);
            r[i] = make_float4(a2.x + b2.x, a2.y + b2.y, a2.z + b2.z, a2.w + b2.w);
        }
        __syncthreads();
        // HMMA: each warp computes gate cols [32*warp, 32*warp+32)
        float cacc[4][4];
#pragma unroll
        for (int nt = 0; nt < 4; nt++) {
            cacc[nt][0] = 0.f; cacc[nt][1] = 0.f; cacc[nt][2] = 0.f; cacc[nt][3] = 0.f;
        }
#pragma unroll
        for (int kk = 0; kk < 4; kk++) {
            // A row-major frags: a0=(g,2t) a1=(g+8,2t) a2=(g,2t+8) a3=(g+8,2t+8)
            unsigned a0 = *reinterpret_cast<const unsigned*>(&h1sm[g * 72 + kk * 16 + 2 * t]);
            unsigned a1 = *reinterpret_cast<const unsigned*>(&h1sm[(g + 8) * 72 + kk * 16 + 2 * t]);
            unsigned a2 = *reinterpret_cast<const unsigned*>(&h1sm[g * 72 + kk * 16 + 2 * t + 8]);
            unsigned a3 = *reinterpret_cast<const unsigned*>(&h1sm[(g + 8) * 72 + kk * 16 + 2 * t + 8]);
#pragma unroll
            for (int nt = 0; nt < 4; nt++) {
                asm volatile(
                    "mma.sync.aligned.m16n8k16.row.col.f32.f16.f16.f32 "
                    "{%0,%1,%2,%3}, {%4,%5,%6,%7}, {%8,%9}, {%0,%1,%2,%3};"
                    : "+f"(cacc[nt][0]), "+f"(cacc[nt][1]),
                      "+f"(cacc[nt][2]), "+f"(cacc[nt][3])
                    : "r"(a0), "r"(a1), "r"(a2), "r"(a3),
                      "r"(bf[kk][nt][0]), "r"(bf[kk][nt][1]));
            }
        }
#pragma unroll
        for (int nt = 0; nt < 4; nt++) {
            int n = (warp * 4 + nt) * 8 + 2 * t;
            *(float2*)&G[g * 268 + n] = make_float2(cacc[nt][0], cacc[nt][1]);
            *(float2*)&G[(g + 8) * 268 + n] = make_float2(cacc[nt][2], cacc[nt][3]);
        }
        __syncthreads();
#pragma unroll
        for (int i = 0; i < 4; i++) {
            float4 gg = *(const float4*)&G[(lp + 4 * i) * 268 + 4 * k];
            float rx = r[i].x + gg.x, ry = r[i].y + gg.y;
            float rz = r[i].z + gg.z, rw = r[i].w + gg.w;
            float c = fsig(ry) * c1v[i] + fsig(rx) * ftanh(rz);
            float h = fsig(rw) * ftanh(c);
            if (n2r[i] >= 0) atomicAdd(&acc[(size_t)n2r[i] * 64 + k], h);
        }
        __syncthreads();
    }
}

// ---------------- BN stats (sum + sumsq per channel) -> outStats ----------------
__global__ void k_stats(const float* __restrict__ x, int R, float* __restrict__ outStats) {
    __shared__ float ssum[256], ssq[256];
    int ch = threadIdx.x & 63;
    int rg = threadIdx.x >> 6;
    float s = 0.0f, sq = 0.0f;
    for (int r = blockIdx.x * 4 + rg; r < R; r += gridDim.x * 4) {
        float v = x[(size_t)r * 64 + ch];
        s += v;
        sq += v * v;
    }
    ssum[threadIdx.x] = s;
    ssq[threadIdx.x] = sq;
    __syncthreads();
    if (threadIdx.x < 64) {
        s = ssum[ch] + ssum[64 + ch] + ssum[128 + ch] + ssum[192 + ch];
        sq = ssq[ch] + ssq[64 + ch] + ssq[128 + ch] + ssq[192 + ch];
        atomicAdd(&outStats[ch], s);
        atomicAdd(&outStats[64 + ch], sq);
    }
}

// ---- fused: out = (relu?)(bn(in; statIn)) @ W + bias; accumulates out stats -> statOut --
__global__ void k_bnmm(const float* __restrict__ in, const float* __restrict__ W,
                       const float* __restrict__ bias, const float* __restrict__ g,
                       const float* __restrict__ bvec, float* __restrict__ out,
                       const float* __restrict__ statIn, float* __restrict__ statOut,
                       int R, int relu) {
    __shared__ float WTs[64 * 64];
    __shared__ float xsn[8 * 64];
    __shared__ float ssum[256], ssq[256];
    int tid = threadIdx.x;
    int c = tid & 63;
    int lp = tid >> 6;
    for (int i = tid; i < 4096; i += 256) {
        int m = i >> 6, cc = i & 63;
        int mg = m >> 2, mj = m & 3;
        WTs[cc * 64 + (((mg ^ (cc & 7)) << 2) | mj)] = W[i];
    }
    __syncthreads();

    const float4* W4 = (const float4*)WTs;
    const float4* x4 = (const float4*)xsn;
    int sw = c & 7;
    int wb = c * 16;
    float invR = 1.0f / (float)R;
    float st_s = 0.0f, st_q = 0.0f;

    for (long long base = (long long)blockIdx.x * 8; base < R; base += (long long)gridDim.x * 8) {
        __syncthreads();
        for (int i = tid; i < 512; i += 256) {
            int row = i >> 6, col = i & 63;
            long long gr = base + row;
            float v = 0.0f;
            if (gr < R) {
                v = in[gr * 64 + col];
                float mean = statIn[col] * invR;
                float var = statIn[64 + col] * invR - mean * mean;
                var = fmaxf(var, 0.0f);
                v = (v - mean) * rsqrtf(var + 1e-5f) * g[col] + bvec[col];
                if (relu) v = fmaxf(v, 0.0f);
            }
            xsn[i] = v;
        }
        __syncthreads();
        float a0 = bias[c], a1 = a0;
#pragma unroll
        for (int mg = 0; mg < 16; mg++) {
            float4 w = W4[wb + (mg ^ sw)];
            float4 x0 = x4[lp * 16 + mg];
            float4 x1 = x4[(lp + 4) * 16 + mg];
            a0 += w.x * x0.x + w.y * x0.y + w.z * x0.z + w.w * x0.w;
            a1 += w.x * x1.x + w.y * x1.y + w.z * x1.z + w.w * x1.w;
        }
        if (base + lp < R) { out[(base + lp) * 64 + c] = a0; st_s += a0; st_q += a0 * a0; }
        if (base + lp + 4 < R) { out[(base + lp + 4) * 64 + c] = a1; st_s += a1; st_q += a1 * a1; }
    }
    __syncthreads();
    ssum[tid] = st_s;
    ssq[tid] = st_q;
    __syncthreads();
    if (tid < 64) {
        float s = ssum[tid] + ssum[64 + tid] + ssum[128 + tid] + ssum[192 + tid];
        float q = ssq[tid] + ssq[64 + tid] + ssq[128 + tid] + ssq[192 + tid];
        atomicAdd(&statOut[tid], s);
        atomicAdd(&statOut[64 + tid], q);
    }
}

// ---------------- BN apply (+optional relu) ----------------
__global__ void k_bnapply(const float* __restrict__ x, float* __restrict__ out,
                          const float* __restrict__ g, const float* __restrict__ b,
                          const float* __restrict__ statIn, int R, int relu) {
    long long i = (long long)blockIdx.x * blockDim.x + threadIdx.x;
    if (i >= (long long)R * 64) return;
    int ch = (int)(i & 63);
    float invR = 1.0f / (float)R;
    float mean = statIn[ch] * invR;
    float var = statIn[64 + ch] * invR - mean * mean;
    var = fmaxf(var, 0.0f);
    float sc = rsqrtf(var + 1e-5f);
    float v = (x[i] - mean) * sc * g[ch] + b[ch];
    if (relu) v = fmaxf(v, 0.0f);
    out[i] = v;
}

// ---------------- attention sums ----------------
__global__ void k_attsum() {
    __shared__ float sh1[256], sh2[256];
    int ch = threadIdx.x & 63;
    int rg = threadIdx.x >> 6;
    float s1 = 0.0f, s2 = 0.0f;
    for (int r = blockIdx.x * 4 + rg; r < NN; r += gridDim.x * 4) {
        long long i = (long long)r * 64 + ch;
        float q = d_W0[i];
        s1 += q * d_W1[i];
        s2 += q * d_W2[i];
    }
    sh1[threadIdx.x] = s1;
    sh2[threadIdx.x] = s2;
    __syncthreads();
    if (threadIdx.x < 64) {
        s1 = sh1[ch] + sh1[64 + ch] + sh1[128 + ch] + sh1[192 + ch];
        s2 = sh2[ch] + sh2[64 + ch] + sh2[128 + ch] + sh2[192 + ch];
        atomicAdd(&d_S[ch], s1);
        atomicAdd(&d_S[64 + ch], s2);
    }
}

// ---------------- attention scores -> softmax weights ----------------
__global__ void k_attfinal(const float* __restrict__ w_att, const float* __restrict__ b_att) {
    int t = threadIdx.x;  // 32 threads
    float scores[2];
#pragma unroll
    for (int j = 0; j < 2; j++) {
        float v0 = d_S[j * 64 + t], v1 = d_S[j * 64 + 32 + t];
        float mn = fminf(v0, v1), mx = fmaxf(v0, v1);
#pragma unroll
        for (int o = 16; o; o >>= 1) {
            mn = fminf(mn, __shfl_xor_sync(0xffffffffu, mn, o));
            mx = fmaxf(mx, __shfl_xor_sync(0xffffffffu, mx, o));
        }
        float inv = 1.0f / (mx - mn + 1e-6f);
        float d = (v0 - mn) * inv * w_att[t] + (v1 - mn) * inv * w_att[32 + t];
#pragma unroll
        for (int o = 16; o; o >>= 1) d += __shfl_xor_sync(0xffffffffu, d, o);
        scores[j] = d + b_att[0];
    }
    if (t == 0) {
        float m = fmaxf(scores[0], scores[1]);
        float e0 = __expf(scores[0] - m), e1 = __expf(scores[1] - m);
        float inv = 1.0f / (e0 + e1);
        d_S[128] = e0 * inv;
        d_S[129] = e1 * inv;
    }
}

// ---------------- combine + global_add_pool ----------------
__global__ void k_pool(const int* __restrict__ batch) {
    long long i = (long long)blockIdx.x * blockDim.x + threadIdx.x;
    if (i >= (long long)NN * 64) return;
    int n = (int)(i >> 6), ch = (int)(i & 63);
    float a0 = d_S[128], a1 = d_S[129];
    float v = d_W0[i] + a0 * d_W1[i] + a1 * d_W2[i];
    atomicAdd(&d_POOL[(size_t)batch[n] * 64 + ch], v);
}

// ---------------- head ----------------
__global__ void k_head(const float* __restrict__ wl1, const float* __restrict__ bl1,
                       const float* __restrict__ wl2, const float* __restrict__ bl2,
                       float* __restrict__ out) {
    __shared__ float row[64], hid[64];
    int g = blockIdx.x, t = threadIdx.x;  // 64 threads
    row[t] = d_POOL[g * 64 + t];
    __syncthreads();
    float a = bl1[t];
#pragma unroll 16
    for (int m = 0; m < 64; m++) a += row[m] * wl1[m * 64 + t];
    hid[t] = fmaxf(a, 0.0f);
    __syncthreads();
    if (t < NCC) {
        float o = bl2[t];
#pragma unroll 16
        for (int m = 0; m < 64; m++) o += hid[m] * wl2[m * NCC + t];
        out[g * NCC + t] = o;
    }
}

// ---------------- launch ----------------
extern "C" void kernel_launch(void* const* d_in, const int* in_sizes, int n_in,
                              void* d_out, int out_size) {
    const float* x         = (const float*)d_in[0];
    const float* edge_attr = (const float*)d_in[1];
    const int*   paths2    = (const int*)d_in[2];
    const int*   ei2       = (const int*)d_in[3];
    const int*   paths3    = (const int*)d_in[4];
    const int*   ei3       = (const int*)d_in[5];
    const int*   batch     = (const int*)d_in[6];
    const float* w_feat = (const float*)d_in[7];
    const float* b_feat = (const float*)d_in[8];
    const float* w_bond = (const float*)d_in[9];
    const float* b_bond = (const float*)d_in[10];
    const float* w_ih   = (const float*)d_in[11];
    const float* w_hh   = (const float*)d_in[12];
    const float* b_ih   = (const float*)d_in[13];
    const float* b_hh   = (const float*)d_in[14];
    const float* bn_g   = (const float*)d_in[15];
    const float* bn_b   = (const float*)d_in[16];
    const float* mlp_w1 = (const float*)d_in[17];
    const float* mlp_b1 = (const float*)d_in[18];
    const float* bn1_g  = (const float*)d_in[19];
    const float* bn1_b  = (const float*)d_in[20];
    const float* mlp_w2 = (const float*)d_in[21];
    const float* mlp_b2 = (const float*)d_in[22];
    const float* bn2_g  = (const float*)d_in[23];
    const float* bn2_b  = (const float*)d_in[24];
    const float* w_att  = (const float*)d_in[25];
    const float* b_att  = (const float*)d_in[26];
    const float* w_l1   = (const float*)d_in[27];
    const float* b_l1   = (const float*)d_in[28];
    const float* w_l2   = (const float*)d_in[29];
    const float* b_l2   = (const float*)d_in[30];
    float* out = (float*)d_out;

    const int SMEM_GT = 256 * 64 * 4 + 8 * 64 * 4;    // 67584
    cudaFuncSetAttribute(k_gtab, cudaFuncAttributeMaxDynamicSharedMemorySize, SMEM_GT);

    float *pW0, *pH0, *pAcc, *pTmp, *pW1, *pW2;
    float *pWxp, *pWhp, *pBiasp, *pStats, *pS, *pPool, *pFwx, *pFbx, *pFwe, *pFbe;
    __half *pGn, *pGe, *pR0, *pC0;
    cudaGetSymbolAddress((void**)&pW0, d_W0);
    cudaGetSymbolAddress((void**)&pGn, d_GNODE);
    cudaGetSymbolAddress((void**)&pGe, d_GEDGE);
    cudaGetSymbolAddress((void**)&pR0, d_R0);
    cudaGetSymbolAddress((void**)&pH0, d_H0);
    cudaGetSymbolAddress((void**)&pC0, d_C0);
    cudaGetSymbolAddress((void**)&pAcc, d_ACC);
    cudaGetSymbolAddress((void**)&pTmp, d_TMP);
    cudaGetSymbolAddress((void**)&pW1, d_W1);
    cudaGetSymbolAddress((void**)&pW2, d_W2);
    cudaGetSymbolAddress((void**)&pWxp, d_WXP);
    cudaGetSymbolAddress((void**)&pWhp, d_WHP);
    cudaGetSymbolAddress((void**)&pBiasp, d_BIASP);
    cudaGetSymbolAddress((void**)&pStats, d_STATS);
    cudaGetSymbolAddress((void**)&pS, d_S);
    cudaGetSymbolAddress((void**)&pPool, d_POOL);
    cudaGetSymbolAddress((void**)&pFwx, d_FWX);
    cudaGetSymbolAddress((void**)&pFbx, d_FBX);
    cudaGetSymbolAddress((void**)&pFwe, d_FWE);
    cudaGetSymbolAddress((void**)&pFbe, d_FBE);
    float* pS0 = pStats;
    float* pS1 = pStats + 128;

    const int NE = NN * 64;
    const int GB_N = (NE + 255) / 256;
    const int PERS = 444;  // 148 SM x 3

    // weights / fused encoders / tables
    k_prep<<<64, 256>>>(w_ih, w_hh, b_ih, b_hh);
    k_fuse<<<38, 256>>>(w_feat, b_feat, w_bond, b_bond, w_ih, b_ih, b_hh);
    k_encode<<<GB_N, 256>>>(x, w_feat, b_feat, pW0, NN);
    k_direct<<<PERS, 256>>>(edge_attr, pFwe, pFbe, pGe, EE);
    k_direct<<<PERS, 256>>>(x, pFwx, pFbx, pGn, NN);

    // ---- conv 0 (L=2): no per-path GEMM ----
    k_h0c0<<<GB_N, 256>>>(pGn, pH0, pC0);
    k_gtab<<<PERS, 256, SMEM_GT>>>(pH0, nullptr, pWhp, nullptr, pR0, NN);
    k_zero<<<GB_N, 256>>>(pAcc, NE);
    k_lstm2<<<(int)(((long long)PP2 * 64 + 255) / 256), 256>>>(paths2, ei2, pGn, pGe, pR0, pC0, pAcc, PP2);
    k_zero<<<1, 256>>>(pStats, 256);
    k_stats<<<512, 256>>>(pAcc, NN, pS0);
    k_bnmm<<<PERS, 256>>>(pAcc, mlp_w1, mlp_b1, bn_g, bn_b, pTmp, pS0, pS1, NN, 0);
    k_zero<<<1, 128>>>(pS0, 128);
    k_bnmm<<<PERS, 256>>>(pTmp, mlp_w2, mlp_b2, bn1_g, bn1_b, pAcc, pS1, pS0, NN, 1);
    k_bnapply<<<GB_N, 256>>>(pAcc, pW1, bn2_g, bn2_b, pS0, NN, 1);

    // ---- conv 1 (L=3): Win blended in gtab; HMMA recurrence in lstm3 ----
    k_gtab<<<PERS, 256, SMEM_GT>>>(pW0, pW1, pWxp, pBiasp, pGn, NN);
    k_h0c0<<<GB_N, 256>>>(pGn, pH0, pC0);
    k_gtab<<<PERS, 256, SMEM_GT>>>(pH0, nullptr, pWhp, nullptr, pR0, NN);
    k_zero<<<GB_N, 256>>>(pAcc, NE);
    k_lstm3<<<PERS, 256>>>(paths3, ei3, pGn, pGe, pR0, pC0, pAcc, PP3);
    k_zero<<<1, 256>>>(pStats, 256);
    k_stats<<<512, 256>>>(pAcc, NN, pS0);
    k_bnmm<<<PERS, 256>>>(pAcc, mlp_w1 + 4096, mlp_b1 + 64, bn_g + 64, bn_b + 64, pTmp, pS0, pS1, NN, 0);
    k_zero<<<1, 128>>>(pS0, 128);
    k_bnmm<<<PERS, 256>>>(pTmp, mlp_w2 + 4096, mlp_b2 + 64, bn1_g + 64, bn1_b + 64, pAcc, pS1, pS0, NN, 1);
    k_bnapply<<<GB_N, 256>>>(pAcc, pW2, bn2_g + 64, bn2_b + 64, pS0, NN, 1);

    // ---- attention + pool + head ----
    k_zero<<<1, 160>>>(pS, 132);
    k_attsum<<<512, 256>>>();
    k_attfinal<<<1, 32>>>(w_att, b_att);
    k_zero<<<(GG * 64 + 255) / 256, 256>>>(pPool, GG * 64);
    k_pool<<<GB_N, 256>>>(batch);
    k_head<<<GG, 64>>>(w_l1, b_l1, w_l2, b_l2, out);
}

// round 13
// speedup vs baseline: 1.3844x; 1.3844x over previous
#include <cuda_runtime.h>
#include <cuda_fp16.h>
#include <cstdint>
#include <math.h>

#define NN   100000
#define EE   200000
#define PP2  250000
#define PP3  500000
#define GG   2048
#define NCC  10

// ---------------- scratch (device globals; no allocations) ----------------
__device__ float  d_W0[NN * 64];
__device__ __half d_GNODE[(size_t)NN * 256];   // fp16 gate tables
__device__ __half d_GEDGE[(size_t)EE * 256];
__device__ __half d_R0[(size_t)NN * 256];
__device__ float  d_H0[NN * 64];
__device__ __half d_C0[NN * 64];
__device__ float  d_ACC[NN * 64];
__device__ float  d_TMP[NN * 64];
__device__ float  d_W1[NN * 64];
__device__ float  d_W2[NN * 64];
__device__ float  d_WXP[256 * 64];
__device__ float  d_WHP[256 * 64];
__device__ float  d_WHHT[64 * 256];
__device__ float  d_BIASP[256];
__device__ float  d_FWX[18 * 256];
__device__ float  d_FBX[256];
__device__ float  d_FWE[18 * 256];
__device__ float  d_FBE[256];
__device__ float  d_STATS[256];   // S0=[0..127], S1=[128..255]
__device__ float  d_S[132];
__device__ float  d_POOL[GG * 64];

__device__ __forceinline__ float fsig(float x) { return 1.0f / (1.0f + __expf(-x)); }
__device__ __forceinline__ float ftanh(float x) { return 2.0f * fsig(2.0f * x) - 1.0f; }

// load 4 consecutive halfs (one gate quad) as float4
__device__ __forceinline__ float4 ldh4(const __half* base, size_t row, int k) {
    uint2 u = *reinterpret_cast<const uint2*>(base + row * 256 + 4 * k);
    __half2 p = *reinterpret_cast<__half2*>(&u.x);
    __half2 q = *reinterpret_cast<__half2*>(&u.y);
    float2 f0 = __half22float2(p), f1 = __half22float2(q);
    return make_float4(f0.x, f0.y, f1.x, f1.y);
}

// ---------------- zero ----------------
__global__ void k_zero(float* p, int n) {
    int i = blockIdx.x * blockDim.x + threadIdx.x;
    if (i < n) p[i] = 0.0f;
}

// ---------------- weight permutation ----------------
__global__ void k_prep(const float* __restrict__ wih, const float* __restrict__ whh,
                       const float* __restrict__ bih, const float* __restrict__ bhh) {
    int i = blockIdx.x * blockDim.x + threadIdx.x;
    if (i >= 256 * 64) return;
    int jp = i >> 6, m = i & 63;
    int k = jp >> 2, q = jp & 3;
    int j = q * 64 + k;
    d_WXP[i] = wih[j * 128 + m];
    d_WHP[i] = whh[j * 64 + m];
    d_WHHT[m * 256 + jp] = whh[j * 64 + m];
    if (m == 0) d_BIASP[jp] = bih[j] + bhh[j];
}

// ---------------- fused encoder->gate weights ----------------
__global__ void k_fuse(const float* __restrict__ wfeat, const float* __restrict__ bfeat,
                       const float* __restrict__ wbond, const float* __restrict__ bbond,
                       const float* __restrict__ wih, const float* __restrict__ bih,
                       const float* __restrict__ bhh) {
    int t = blockIdx.x * blockDim.x + threadIdx.x;
    if (t >= 2 * 19 * 256) return;
    int jp = t & 255;
    int f = (t >> 8) % 19;
    int mat = t / (19 * 256);
    int k = jp >> 2, q = jp & 3;
    int j = q * 64 + k;
    const float* wrow = wih + j * 128 + (mat ? 64 : 0);
    float s = 0.0f;
    if (f < 18) {
        const float* src = mat ? wbond : wfeat;
#pragma unroll 16
        for (int m = 0; m < 64; m++) s += src[f * 64 + m] * wrow[m];
        (mat ? d_FWE : d_FWX)[f * 256 + jp] = s;
    } else {
        const float* bsrc = mat ? bbond : bfeat;
#pragma unroll 16
        for (int m = 0; m < 64; m++) s += bsrc[m] * wrow[m];
        if (!mat) s += bih[j] + bhh[j];
        (mat ? d_FBE : d_FBX)[jp] = s;
    }
}

// ---------------- encoder for W0 ----------------
__global__ void k_encode(const float* __restrict__ in, const float* __restrict__ w,
                         const float* __restrict__ b, float* __restrict__ out, int R) {
    long long tid = (long long)blockIdx.x * blockDim.x + threadIdx.x;
    if (tid >= (long long)R * 64) return;
    int ch = (int)(tid & 63);
    long long r = tid >> 6;
    const float* xr = in + r * 18;
    float acc = b[ch];
#pragma unroll
    for (int j = 0; j < 18; j++) acc += xr[j] * w[j * 64 + ch];
    out[tid] = acc;
}

// ---------------- direct gate table: out[R,256] = in[R,18] @ FW + FB (half out) ------
__global__ void __launch_bounds__(256) k_direct(
        const float* __restrict__ in, const float* __restrict__ FW,
        const float* __restrict__ FB, __half* __restrict__ out, int R) {
    __shared__ float FWs[18 * 256];
    __shared__ float Fbs[256];
    __shared__ float xs[16 * 18];
    int tid = threadIdx.x;
    for (int i = tid; i < 18 * 256; i += 256) FWs[i] = FW[i];
    Fbs[tid] = FB[tid];

    long long stride = (long long)gridDim.x * 16;
    long long base = (long long)blockIdx.x * 16;
    auto ldx = [&](long long b, int i) -> float {
        int row = i / 18, col = i - row * 18;
        long long gr = b + row;
        return (i < 288 && gr < R) ? in[gr * 18 + col] : 0.0f;
    };
    float v0 = ldx(base, tid), v1 = ldx(base, tid + 256);
    __syncthreads();

    for (; base < R; base += stride) {
        xs[tid < 288 ? tid : 0] = tid < 288 ? v0 : xs[0];
        if (tid < 32) xs[tid + 256] = v1;
        __syncthreads();
        long long nb = base + stride;
        v0 = ldx(nb, tid); v1 = ldx(nb, tid + 256);
        float acc[16];
#pragma unroll
        for (int r = 0; r < 16; r++) acc[r] = Fbs[tid];
#pragma unroll
        for (int f = 0; f < 18; f++) {
            float w = FWs[f * 256 + tid];
#pragma unroll
            for (int r = 0; r < 16; r++) acc[r] += w * xs[r * 18 + f];
        }
#pragma unroll
        for (int r = 0; r < 16; r++)
            if (base + r < R) out[(base + r) * 256 + tid] = __float2half(acc[r]);
        __syncthreads();
    }
}

// ---------------- HMMA gate tables: out[R,256] = blend(in,in2)[R,64] @ W[256,64]^T (+bias) --
// 32-row tiles. B (W) stationary in register fragments; A fp16 in smem (pad 72).
__global__ void __launch_bounds__(256) k_gtabmma(
        const float* __restrict__ in, const float* __restrict__ in2,
        const float* __restrict__ W, const float* __restrict__ bias,
        __half* __restrict__ out, int R) {
    __shared__ __half Asm[32 * 72];
    int tid = threadIdx.x;
    int warp = tid >> 5, lane = tid & 31;
    int g = lane >> 2, t = lane & 3;

    // stationary B fragments: warp owns output cols [32*warp, 32*warp+32)
    // B[k][n] = W[n*64 + k]  (m16n8k16.row.col layout, verified in R12)
    unsigned bf[4][4][2];
#pragma unroll
    for (int kk = 0; kk < 4; kk++)
#pragma unroll
        for (int nt = 0; nt < 4; nt++) {
            int n = warp * 32 + nt * 8 + g;
            int k0 = kk * 16 + 2 * t;
            __half2 b0 = __floats2half2_rn(W[n * 64 + k0], W[n * 64 + k0 + 1]);
            __half2 b1 = __floats2half2_rn(W[n * 64 + k0 + 8], W[n * 64 + k0 + 9]);
            bf[kk][nt][0] = *reinterpret_cast<unsigned*>(&b0);
            bf[kk][nt][1] = *reinterpret_cast<unsigned*>(&b1);
        }
    float bb[4][2];
#pragma unroll
    for (int nt = 0; nt < 4; nt++) {
        int n = warp * 32 + nt * 8 + 2 * t;
        bb[nt][0] = bias ? bias[n] : 0.0f;
        bb[nt][1] = bias ? bias[n + 1] : 0.0f;
    }

    long long stride = (long long)gridDim.x * 32;
    long long base = (long long)blockIdx.x * 32;
    auto ldx = [&](long long b, int i) -> float {
        int row = i >> 6, col = i & 63;
        long long gr = b + row;
        float v = 0.0f;
        if (gr < R) {
            v = in[gr * 64 + col];
            if (in2) v = 0.75f * v - 0.25f * in2[gr * 64 + col];
        }
        return v;
    };
    float v[8];
#pragma unroll
    for (int j = 0; j < 8; j++) v[j] = ldx(base, tid + j * 256);

    for (; base < R; base += stride) {
#pragma unroll
        for (int j = 0; j < 8; j++) {
            int i = tid + j * 256;
            Asm[(i >> 6) * 72 + (i & 63)] = __float2half(v[j]);
        }
        __syncthreads();
        long long nb = base + stride;
#pragma unroll
        for (int j = 0; j < 8; j++) v[j] = ldx(nb, tid + j * 256);

        float cacc[2][4][4];
#pragma unroll
        for (int mt = 0; mt < 2; mt++)
#pragma unroll
            for (int nt = 0; nt < 4; nt++) {
                cacc[mt][nt][0] = bb[nt][0]; cacc[mt][nt][1] = bb[nt][1];
                cacc[mt][nt][2] = bb[nt][0]; cacc[mt][nt][3] = bb[nt][1];
            }
#pragma unroll
        for (int mt = 0; mt < 2; mt++)
#pragma unroll
            for (int kk = 0; kk < 4; kk++) {
                unsigned a0 = *reinterpret_cast<const unsigned*>(&Asm[(mt * 16 + g) * 72 + kk * 16 + 2 * t]);
                unsigned a1 = *reinterpret_cast<const unsigned*>(&Asm[(mt * 16 + g + 8) * 72 + kk * 16 + 2 * t]);
                unsigned a2 = *reinterpret_cast<const unsigned*>(&Asm[(mt * 16 + g) * 72 + kk * 16 + 2 * t + 8]);
                unsigned a3 = *reinterpret_cast<const unsigned*>(&Asm[(mt * 16 + g + 8) * 72 + kk * 16 + 2 * t + 8]);
#pragma unroll
                for (int nt = 0; nt < 4; nt++) {
                    asm volatile(
                        "mma.sync.aligned.m16n8k16.row.col.f32.f16.f16.f32 "
                        "{%0,%1,%2,%3}, {%4,%5,%6,%7}, {%8,%9}, {%0,%1,%2,%3};"
                        : "+f"(cacc[mt][nt][0]), "+f"(cacc[mt][nt][1]),
                          "+f"(cacc[mt][nt][2]), "+f"(cacc[mt][nt][3])
                        : "r"(a0), "r"(a1), "r"(a2), "r"(a3),
                          "r"(bf[kk][nt][0]), "r"(bf[kk][nt][1]));
                }
            }
#pragma unroll
        for (int mt = 0; mt < 2; mt++)
#pragma unroll
            for (int nt = 0; nt < 4; nt++) {
                int n = warp * 32 + nt * 8 + 2 * t;
                long long r0 = base + mt * 16 + g;
                long long r1 = r0 + 8;
                if (r0 < R) {
                    __half2 h = __floats2half2_rn(cacc[mt][nt][0], cacc[mt][nt][1]);
                    *reinterpret_cast<__half2*>(&out[r0 * 256 + n]) = h;
                }
                if (r1 < R) {
                    __half2 h = __floats2half2_rn(cacc[mt][nt][2], cacc[mt][nt][3]);
                    *reinterpret_cast<__half2*>(&out[r1 * 256 + n]) = h;
                }
            }
        __syncthreads();
    }
}

// ---------------- per-node step-0 state from (half) gate table ----------------
__global__ void k_h0c0(const __half* __restrict__ gnode, float* __restrict__ h0,
                       __half* __restrict__ c0) {
    long long gid = (long long)blockIdx.x * blockDim.x + threadIdx.x;
    if (gid >= (long long)NN * 64) return;
    uint2 u = reinterpret_cast<const uint2*>(gnode)[gid];
    __half2 p = *reinterpret_cast<__half2*>(&u.x);
    __half2 q = *reinterpret_cast<__half2*>(&u.y);
    float2 f0 = __half22float2(p), f1 = __half22float2(q);
    float c = fsig(f0.x) * ftanh(f1.x);
    float h = fsig(f1.y) * ftanh(c);
    c0[gid] = __float2half(c);
    h0[gid] = h;
}

// ---------------- conv0: pure gather + elementwise LSTM step 1 ----------------
__global__ void k_lstm2(const int* __restrict__ paths, const int* __restrict__ ei,
                        const __half* __restrict__ gnode, const __half* __restrict__ gedge,
                        const __half* __restrict__ r0tab, const __half* __restrict__ c0tab,
                        float* __restrict__ acc, int P) {
    long long gid = (long long)blockIdx.x * blockDim.x + threadIdx.x;
    if (gid >= (long long)P * 64) return;
    int k = (int)(gid & 63);
    long long p = gid >> 6;
    int n0 = paths[p * 2], n1 = paths[p * 2 + 1], e0 = ei[p];
    float4 a = ldh4(gnode, (size_t)n1, k);
    float4 b = ldh4(gedge, (size_t)e0, k);
    float4 r = ldh4(r0tab, (size_t)n0, k);
    float c0 = __half2float(c0tab[(size_t)n0 * 64 + k]);
    float gx = a.x + b.x + r.x, gy = a.y + b.y + r.y;
    float gz = a.z + b.z + r.z, gw = a.w + b.w + r.w;
    float c1 = fsig(gy) * c0 + fsig(gx) * ftanh(gz);
    float h1 = fsig(gw) * ftanh(c1);
    atomicAdd(&acc[(size_t)n1 * 64 + k], h1);
}

// ---------------- conv1 (R10-proven 16-path FFMA form, half gathers) ----------------
#define ACC4(W, C) \
    r0.x += a0.C * W.x; r0.y += a0.C * W.y; r0.z += a0.C * W.z; r0.w += a0.C * W.w; \
    r1.x += a1.C * W.x; r1.y += a1.C * W.y; r1.z += a1.C * W.z; r1.w += a1.C * W.w; \
    r2.x += a2.C * W.x; r2.y += a2.C * W.y; r2.z += a2.C * W.z; r2.w += a2.C * W.w; \
    r3.x += a3.C * W.x; r3.y += a3.C * W.y; r3.z += a3.C * W.z; r3.w += a3.C * W.w;

__global__ void k_lstm3(const int* __restrict__ paths, const int* __restrict__ ei,
                        const __half* __restrict__ gnode, const __half* __restrict__ gedge,
                        const __half* __restrict__ r0tab, const __half* __restrict__ c0tab,
                        float* __restrict__ acc, int P) {
    extern __shared__ float sh[];
    float* whhT = sh;             // [64][256]
    float* hsh = sh + 64 * 256;   // [16][64]
    int tid = threadIdx.x;
    for (int i = tid; i < 64 * 256; i += blockDim.x) whhT[i] = d_WHHT[i];
    __syncthreads();

    int k = tid & 63;
    int lp = tid >> 6;
    const float4* whhT4 = (const float4*)whhT;

    for (long long base = (long long)blockIdx.x * 16; base < P; base += (long long)gridDim.x * 16) {
        long long p[4];
        bool valid[4];
        int n0[4], n1[4], n2[4], e0[4], e1[4];
#pragma unroll
        for (int i = 0; i < 4; i++) {
            p[i] = base + lp + 4 * i;
            valid[i] = p[i] < P;
            long long pi = valid[i] ? p[i] : 0;
            n0[i] = paths[pi * 3]; n1[i] = paths[pi * 3 + 1]; n2[i] = paths[pi * 3 + 2];
            e0[i] = ei[pi * 2]; e1[i] = ei[pi * 2 + 1];
        }
        float4 g1[4];
        float c0v[4];
#pragma unroll
        for (int i = 0; i < 4; i++) {
            float4 a = ldh4(gnode, (size_t)n1[i], k);
            float4 b = ldh4(gedge, (size_t)e0[i], k);
            float4 r = ldh4(r0tab, (size_t)n0[i], k);
            g1[i] = make_float4(a.x + b.x + r.x, a.y + b.y + r.y,
                                a.z + b.z + r.z, a.w + b.w + r.w);
            c0v[i] = __half2float(c0tab[(size_t)n0[i] * 64 + k]);
        }
        float4 r0, r1, r2, r3;
#pragma unroll
        for (int i = 0; i < 4; i++) {
            float4 a = ldh4(gnode, (size_t)n2[i], k);
            float4 b = ldh4(gedge, (size_t)e1[i], k);
            float4 v = make_float4(a.x + b.x, a.y + b.y, a.z + b.z, a.w + b.w);
            if (i == 0) r0 = v; else if (i == 1) r1 = v; else if (i == 2) r2 = v; else r3 = v;
        }
        float c1[4], h1[4];
#pragma unroll
        for (int i = 0; i < 4; i++) {
            float c = fsig(g1[i].y) * c0v[i] + fsig(g1[i].x) * ftanh(g1[i].z);
            c1[i] = c;
            h1[i] = fsig(g1[i].w) * ftanh(c);
        }
        __syncthreads();
#pragma unroll
        for (int i = 0; i < 4; i++) hsh[(lp + 4 * i) * 64 + k] = h1[i];
        __syncthreads();
        const float4* h0r = (const float4*)(hsh + (lp + 0) * 64);
        const float4* h1r = (const float4*)(hsh + (lp + 4) * 64);
        const float4* h2r = (const float4*)(hsh + (lp + 8) * 64);
        const float4* h3r = (const float4*)(hsh + (lp + 12) * 64);
#pragma unroll
        for (int mq = 0; mq < 16; mq++) {
            float4 a0 = h0r[mq], a1 = h1r[mq], a2 = h2r[mq], a3 = h3r[mq];
            {
                float4 w = whhT4[(4 * mq + 0) * 64 + k];
                ACC4(w, x)
            }
            {
                float4 w = whhT4[(4 * mq + 1) * 64 + k];
                ACC4(w, y)
            }
            {
                float4 w = whhT4[(4 * mq + 2) * 64 + k];
                ACC4(w, z)
            }
            {
                float4 w = whhT4[(4 * mq + 3) * 64 + k];
                ACC4(w, w)
            }
        }
#pragma unroll
        for (int i = 0; i < 4; i++) {
            float4 r = (i == 0) ? r0 : (i == 1) ? r1 : (i == 2) ? r2 : r3;
            float c = fsig(r.y) * c1[i] + fsig(r.x) * ftanh(r.z);
            float h = fsig(r.w) * ftanh(c);
            if (valid[i]) atomicAdd(&acc[(size_t)n2[i] * 64 + k], h);
        }
    }
}

// ---------------- BN stats (sum + sumsq per channel) -> outStats ----------------
__global__ void k_stats(const float* __restrict__ x, int R, float* __restrict__ outStats) {
    __shared__ float ssum[256], ssq[256];
    int ch = threadIdx.x & 63;
    int rg = threadIdx.x >> 6;
    float s = 0.0f, sq = 0.0f;
    for (int r = blockIdx.x * 4 + rg; r < R; r += gridDim.x * 4) {
        float v = x[(size_t)r * 64 + ch];
        s += v;
        sq += v * v;
    }
    ssum[threadIdx.x] = s;
    ssq[threadIdx.x] = sq;
    __syncthreads();
    if (threadIdx.x < 64) {
        s = ssum[ch] + ssum[64 + ch] + ssum[128 + ch] + ssum[192 + ch];
        sq = ssq[ch] + ssq[64 + ch] + ssq[128 + ch] + ssq[192 + ch];
        atomicAdd(&outStats[ch], s);
        atomicAdd(&outStats[64 + ch], sq);
    }
}

// ---- fused: out = (relu?)(bn(in; statIn)) @ W + bias; accumulates out stats -> statOut --
__global__ void k_bnmm(const float* __restrict__ in, const float* __restrict__ W,
                       const float* __restrict__ bias, const float* __restrict__ g,
                       const float* __restrict__ bvec, float* __restrict__ out,
                       const float* __restrict__ statIn, float* __restrict__ statOut,
                       int R, int relu) {
    __shared__ float WTs[64 * 64];
    __shared__ float xsn[8 * 64];
    __shared__ float ssum[256], ssq[256];
    int tid = threadIdx.x;
    int c = tid & 63;
    int lp = tid >> 6;
    for (int i = tid; i < 4096; i += 256) {
        int m = i >> 6, cc = i & 63;
        int mg = m >> 2, mj = m & 3;
        WTs[cc * 64 + (((mg ^ (cc & 7)) << 2) | mj)] = W[i];
    }
    __syncthreads();

    const float4* W4 = (const float4*)WTs;
    const float4* x4 = (const float4*)xsn;
    int sw = c & 7;
    int wb = c * 16;
    float invR = 1.0f / (float)R;
    float st_s = 0.0f, st_q = 0.0f;

    for (long long base = (long long)blockIdx.x * 8; base < R; base += (long long)gridDim.x * 8) {
        __syncthreads();
        for (int i = tid; i < 512; i += 256) {
            int row = i >> 6, col = i & 63;
            long long gr = base + row;
            float v = 0.0f;
            if (gr < R) {
                v = in[gr * 64 + col];
                float mean = statIn[col] * invR;
                float var = statIn[64 + col] * invR - mean * mean;
                var = fmaxf(var, 0.0f);
                v = (v - mean) * rsqrtf(var + 1e-5f) * g[col] + bvec[col];
                if (relu) v = fmaxf(v, 0.0f);
            }
            xsn[i] = v;
        }
        __syncthreads();
        float a0 = bias[c], a1 = a0;
#pragma unroll
        for (int mg = 0; mg < 16; mg++) {
            float4 w = W4[wb + (mg ^ sw)];
            float4 x0 = x4[lp * 16 + mg];
            float4 x1 = x4[(lp + 4) * 16 + mg];
            a0 += w.x * x0.x + w.y * x0.y + w.z * x0.z + w.w * x0.w;
            a1 += w.x * x1.x + w.y * x1.y + w.z * x1.z + w.w * x1.w;
        }
        if (base + lp < R) { out[(base + lp) * 64 + c] = a0; st_s += a0; st_q += a0 * a0; }
        if (base + lp + 4 < R) { out[(base + lp + 4) * 64 + c] = a1; st_s += a1; st_q += a1 * a1; }
    }
    __syncthreads();
    ssum[tid] = st_s;
    ssq[tid] = st_q;
    __syncthreads();
    if (tid < 64) {
        float s = ssum[tid] + ssum[64 + tid] + ssum[128 + tid] + ssum[192 + tid];
        float q = ssq[tid] + ssq[64 + tid] + ssq[128 + tid] + ssq[192 + tid];
        atomicAdd(&statOut[tid], s);
        atomicAdd(&statOut[64 + tid], q);
    }
}

// ---------------- BN apply (+optional relu) ----------------
__global__ void k_bnapply(const float* __restrict__ x, float* __restrict__ out,
                          const float* __restrict__ g, const float* __restrict__ b,
                          const float* __restrict__ statIn, int R, int relu) {
    long long i = (long long)blockIdx.x * blockDim.x + threadIdx.x;
    if (i >= (long long)R * 64) return;
    int ch = (int)(i & 63);
    float invR = 1.0f / (float)R;
    float mean = statIn[ch] * invR;
    float var = statIn[64 + ch] * invR - mean * mean;
    var = fmaxf(var, 0.0f);
    float sc = rsqrtf(var + 1e-5f);
    float v = (x[i] - mean) * sc * g[ch] + b[ch];
    if (relu) v = fmaxf(v, 0.0f);
    out[i] = v;
}

// ---------------- attention sums ----------------
__global__ void k_attsum() {
    __shared__ float sh1[256], sh2[256];
    int ch = threadIdx.x & 63;
    int rg = threadIdx.x >> 6;
    float s1 = 0.0f, s2 = 0.0f;
    for (int r = blockIdx.x * 4 + rg; r < NN; r += gridDim.x * 4) {
        long long i = (long long)r * 64 + ch;
        float q = d_W0[i];
        s1 += q * d_W1[i];
        s2 += q * d_W2[i];
    }
    sh1[threadIdx.x] = s1;
    sh2[threadIdx.x] = s2;
    __syncthreads();
    if (threadIdx.x < 64) {
        s1 = sh1[ch] + sh1[64 + ch] + sh1[128 + ch] + sh1[192 + ch];
        s2 = sh2[ch] + sh2[64 + ch] + sh2[128 + ch] + sh2[192 + ch];
        atomicAdd(&d_S[ch], s1);
        atomicAdd(&d_S[64 + ch], s2);
    }
}

// ---------------- attention scores -> softmax weights ----------------
__global__ void k_attfinal(const float* __restrict__ w_att, const float* __restrict__ b_att) {
    int t = threadIdx.x;  // 32 threads
    float scores[2];
#pragma unroll
    for (int j = 0; j < 2; j++) {
        float v0 = d_S[j * 64 + t], v1 = d_S[j * 64 + 32 + t];
        float mn = fminf(v0, v1), mx = fmaxf(v0, v1);
#pragma unroll
        for (int o = 16; o; o >>= 1) {
            mn = fminf(mn, __shfl_xor_sync(0xffffffffu, mn, o));
            mx = fmaxf(mx, __shfl_xor_sync(0xffffffffu, mx, o));
        }
        float inv = 1.0f / (mx - mn + 1e-6f);
        float d = (v0 - mn) * inv * w_att[t] + (v1 - mn) * inv * w_att[32 + t];
#pragma unroll
        for (int o = 16; o; o >>= 1) d += __shfl_xor_sync(0xffffffffu, d, o);
        scores[j] = d + b_att[0];
    }
    if (t == 0) {
        float m = fmaxf(scores[0], scores[1]);
        float e0 = __expf(scores[0] - m), e1 = __expf(scores[1] - m);
        float inv = 1.0f / (e0 + e1);
        d_S[128] = e0 * inv;
        d_S[129] = e1 * inv;
    }
}

// ---------------- combine + global_add_pool ----------------
__global__ void k_pool(const int* __restrict__ batch) {
    long long i = (long long)blockIdx.x * blockDim.x + threadIdx.x;
    if (i >= (long long)NN * 64) return;
    int n = (int)(i >> 6), ch = (int)(i & 63);
    float a0 = d_S[128], a1 = d_S[129];
    float v = d_W0[i] + a0 * d_W1[i] + a1 * d_W2[i];
    atomicAdd(&d_POOL[(size_t)batch[n] * 64 + ch], v);
}

// ---------------- head ----------------
__global__ void k_head(const float* __restrict__ wl1, const float* __restrict__ bl1,
                       const float* __restrict__ wl2, const float* __restrict__ bl2,
                       float* __restrict__ out) {
    __shared__ float row[64], hid[64];
    int g = blockIdx.x, t = threadIdx.x;  // 64 threads
    row[t] = d_POOL[g * 64 + t];
    __syncthreads();
    float a = bl1[t];
#pragma unroll 16
    for (int m = 0; m < 64; m++) a += row[m] * wl1[m * 64 + t];
    hid[t] = fmaxf(a, 0.0f);
    __syncthreads();
    if (t < NCC) {
        float o = bl2[t];
#pragma unroll 16
        for (int m = 0; m < 64; m++) o += hid[m] * wl2[m * NCC + t];
        out[g * NCC + t] = o;
    }
}

// ---------------- launch ----------------
extern "C" void kernel_launch(void* const* d_in, const int* in_sizes, int n_in,
                              void* d_out, int out_size) {
    const float* x         = (const float*)d_in[0];
    const float* edge_attr = (const float*)d_in[1];
    const int*   paths2    = (const int*)d_in[2];
    const int*   ei2       = (const int*)d_in[3];
    const int*   paths3    = (const int*)d_in[4];
    const int*   ei3       = (const int*)d_in[5];
    const int*   batch     = (const int*)d_in[6];
    const float* w_feat = (const float*)d_in[7];
    const float* b_feat = (const float*)d_in[8];
    const float* w_bond = (const float*)d_in[9];
    const float* b_bond = (const float*)d_in[10];
    const float* w_ih   = (const float*)d_in[11];
    const float* w_hh   = (const float*)d_in[12];
    const float* b_ih   = (const float*)d_in[13];
    const float* b_hh   = (const float*)d_in[14];
    const float* bn_g   = (const float*)d_in[15];
    const float* bn_b   = (const float*)d_in[16];
    const float* mlp_w1 = (const float*)d_in[17];
    const float* mlp_b1 = (const float*)d_in[18];
    const float* bn1_g  = (const float*)d_in[19];
    const float* bn1_b  = (const float*)d_in[20];
    const float* mlp_w2 = (const float*)d_in[21];
    const float* mlp_b2 = (const float*)d_in[22];
    const float* bn2_g  = (const float*)d_in[23];
    const float* bn2_b  = (const float*)d_in[24];
    const float* w_att  = (const float*)d_in[25];
    const float* b_att  = (const float*)d_in[26];
    const float* w_l1   = (const float*)d_in[27];
    const float* b_l1   = (const float*)d_in[28];
    const float* w_l2   = (const float*)d_in[29];
    const float* b_l2   = (const float*)d_in[30];
    float* out = (float*)d_out;

    const int SMEM_LS = 64 * 256 * 4 + 16 * 64 * 4;   // 69632
    cudaFuncSetAttribute(k_lstm3, cudaFuncAttributeMaxDynamicSharedMemorySize, SMEM_LS);

    float *pW0, *pH0, *pAcc, *pTmp, *pW1, *pW2;
    float *pWxp, *pWhp, *pBiasp, *pStats, *pS, *pPool, *pFwx, *pFbx, *pFwe, *pFbe;
    __half *pGn, *pGe, *pR0, *pC0;
    cudaGetSymbolAddress((void**)&pW0, d_W0);
    cudaGetSymbolAddress((void**)&pGn, d_GNODE);
    cudaGetSymbolAddress((void**)&pGe, d_GEDGE);
    cudaGetSymbolAddress((void**)&pR0, d_R0);
    cudaGetSymbolAddress((void**)&pH0, d_H0);
    cudaGetSymbolAddress((void**)&pC0, d_C0);
    cudaGetSymbolAddress((void**)&pAcc, d_ACC);
    cudaGetSymbolAddress((void**)&pTmp, d_TMP);
    cudaGetSymbolAddress((void**)&pW1, d_W1);
    cudaGetSymbolAddress((void**)&pW2, d_W2);
    cudaGetSymbolAddress((void**)&pWxp, d_WXP);
    cudaGetSymbolAddress((void**)&pWhp, d_WHP);
    cudaGetSymbolAddress((void**)&pBiasp, d_BIASP);
    cudaGetSymbolAddress((void**)&pStats, d_STATS);
    cudaGetSymbolAddress((void**)&pS, d_S);
    cudaGetSymbolAddress((void**)&pPool, d_POOL);
    cudaGetSymbolAddress((void**)&pFwx, d_FWX);
    cudaGetSymbolAddress((void**)&pFbx, d_FBX);
    cudaGetSymbolAddress((void**)&pFwe, d_FWE);
    cudaGetSymbolAddress((void**)&pFbe, d_FBE);
    float* pS0 = pStats;
    float* pS1 = pStats + 128;

    const int NE = NN * 64;
    const int GB_N = (NE + 255) / 256;
    const int PERS = 444;  // 148 SM x 3

    // weights / fused encoders / tables
    k_prep<<<64, 256>>>(w_ih, w_hh, b_ih, b_hh);
    k_fuse<<<38, 256>>>(w_feat, b_feat, w_bond, b_bond, w_ih, b_ih, b_hh);
    k_encode<<<GB_N, 256>>>(x, w_feat, b_feat, pW0, NN);
    k_direct<<<PERS, 256>>>(edge_attr, pFwe, pFbe, pGe, EE);
    k_direct<<<PERS, 256>>>(x, pFwx, pFbx, pGn, NN);

    // ---- conv 0 (L=2): no per-path GEMM ----
    k_h0c0<<<GB_N, 256>>>(pGn, pH0, pC0);
    k_gtabmma<<<PERS, 256>>>(pH0, nullptr, pWhp, nullptr, pR0, NN);
    k_zero<<<GB_N, 256>>>(pAcc, NE);
    k_lstm2<<<(int)(((long long)PP2 * 64 + 255) / 256), 256>>>(paths2, ei2, pGn, pGe, pR0, pC0, pAcc, PP2);
    k_zero<<<1, 256>>>(pStats, 256);
    k_stats<<<512, 256>>>(pAcc, NN, pS0);
    k_bnmm<<<PERS, 256>>>(pAcc, mlp_w1, mlp_b1, bn_g, bn_b, pTmp, pS0, pS1, NN, 0);
    k_zero<<<1, 128>>>(pS0, 128);
    k_bnmm<<<PERS, 256>>>(pTmp, mlp_w2, mlp_b2, bn1_g, bn1_b, pAcc, pS1, pS0, NN, 1);
    k_bnapply<<<GB_N, 256>>>(pAcc, pW1, bn2_g, bn2_b, pS0, NN, 1);

    // ---- conv 1 (L=3): Win blended in gtabmma; FFMA recurrence in lstm3 ----
    k_gtabmma<<<PERS, 256>>>(pW0, pW1, pWxp, pBiasp, pGn, NN);
    k_h0c0<<<GB_N, 256>>>(pGn, pH0, pC0);
    k_gtabmma<<<PERS, 256>>>(pH0, nullptr, pWhp, nullptr, pR0, NN);
    k_zero<<<GB_N, 256>>>(pAcc, NE);
    k_lstm3<<<PERS, 256, SMEM_LS>>>(paths3, ei3, pGn, pGe, pR0, pC0, pAcc, PP3);
    k_zero<<<1, 256>>>(pStats, 256);
    k_stats<<<512, 256>>>(pAcc, NN, pS0);
    k_bnmm<<<PERS, 256>>>(pAcc, mlp_w1 + 4096, mlp_b1 + 64, bn_g + 64, bn_b + 64, pTmp, pS0, pS1, NN, 0);
    k_zero<<<1, 128>>>(pS0, 128);
    k_bnmm<<<PERS, 256>>>(pTmp, mlp_w2 + 4096, mlp_b2 + 64, bn1_g + 64, bn1_b + 64, pAcc, pS1, pS0, NN, 1);
    k_bnapply<<<GB_N, 256>>>(pAcc, pW2, bn2_g + 64, bn2_b + 64, pS0, NN, 1);

    // ---- attention + pool + head ----
    k_zero<<<1, 160>>>(pS, 132);
    k_attsum<<<512, 256>>>();
    k_attfinal<<<1, 32>>>(w_att, b_att);
    k_zero<<<(GG * 64 + 255) / 256, 256>>>(pPool, GG * 64);
    k_pool<<<GB_N, 256>>>(batch);
    k_head<<<GG, 64>>>(w_l1, b_l1, w_l2, b_l2, out);
}

// round 14
// speedup vs baseline: 1.3895x; 1.0037x over previous
#include <cuda_runtime.h>
#include <cuda_fp16.h>
#include <cstdint>
#include <math.h>

#define NN   100000
#define EE   200000
#define PP2  250000
#define PP3  500000
#define GG   2048
#define NCC  10

// ---------------- scratch (device globals; no allocations) ----------------
__device__ float  d_W0[NN * 64];
__device__ __half d_GNODE[(size_t)NN * 256];   // fp16 gate tables
__device__ __half d_GEDGE[(size_t)EE * 256];
__device__ __half d_R0[(size_t)NN * 256];
__device__ __half d_H0[NN * 64];
__device__ __half d_C0[NN * 64];
__device__ float  d_ACC[NN * 64];
__device__ float  d_TMP[NN * 64];
__device__ float  d_W1[NN * 64];
__device__ float  d_W2[NN * 64];
__device__ float  d_WXP[256 * 64];
__device__ float  d_WHP[256 * 64];
__device__ float  d_WHHT[64 * 256];
__device__ float  d_BIASP[256];
__device__ float  d_FWX[18 * 256];
__device__ float  d_FBX[256];
__device__ float  d_FWE[18 * 256];
__device__ float  d_FBE[256];
__device__ float  d_STATS[256];   // S0=[0..127], S1=[128..255]
__device__ float  d_S[132];
__device__ float  d_POOL[GG * 64];

__device__ __forceinline__ float fsig(float x) { return 1.0f / (1.0f + __expf(-x)); }
__device__ __forceinline__ float ftanh(float x) { return 2.0f * fsig(2.0f * x) - 1.0f; }

// load 4 consecutive halfs (one gate quad) as float4
__device__ __forceinline__ float4 ldh4(const __half* base, size_t row, int k) {
    uint2 u = *reinterpret_cast<const uint2*>(base + row * 256 + 4 * k);
    __half2 p = *reinterpret_cast<__half2*>(&u.x);
    __half2 q = *reinterpret_cast<__half2*>(&u.y);
    float2 f0 = __half22float2(p), f1 = __half22float2(q);
    return make_float4(f0.x, f0.y, f1.x, f1.y);
}

// ---------------- zero ----------------
__global__ void k_zero(float* p, int n) {
    int i = blockIdx.x * blockDim.x + threadIdx.x;
    if (i < n) p[i] = 0.0f;
}

// ---------------- weight permutation ----------------
__global__ void k_prep(const float* __restrict__ wih, const float* __restrict__ whh,
                       const float* __restrict__ bih, const float* __restrict__ bhh) {
    int i = blockIdx.x * blockDim.x + threadIdx.x;
    if (i >= 256 * 64) return;
    int jp = i >> 6, m = i & 63;
    int k = jp >> 2, q = jp & 3;
    int j = q * 64 + k;
    d_WXP[i] = wih[j * 128 + m];
    d_WHP[i] = whh[j * 64 + m];
    d_WHHT[m * 256 + jp] = whh[j * 64 + m];
    if (m == 0) d_BIASP[jp] = bih[j] + bhh[j];
}

// ---------------- fused encoder->gate weights ----------------
__global__ void k_fuse(const float* __restrict__ wfeat, const float* __restrict__ bfeat,
                       const float* __restrict__ wbond, const float* __restrict__ bbond,
                       const float* __restrict__ wih, const float* __restrict__ bih,
                       const float* __restrict__ bhh) {
    int t = blockIdx.x * blockDim.x + threadIdx.x;
    if (t >= 2 * 19 * 256) return;
    int jp = t & 255;
    int f = (t >> 8) % 19;
    int mat = t / (19 * 256);
    int k = jp >> 2, q = jp & 3;
    int j = q * 64 + k;
    const float* wrow = wih + j * 128 + (mat ? 64 : 0);
    float s = 0.0f;
    if (f < 18) {
        const float* src = mat ? wbond : wfeat;
#pragma unroll 16
        for (int m = 0; m < 64; m++) s += src[f * 64 + m] * wrow[m];
        (mat ? d_FWE : d_FWX)[f * 256 + jp] = s;
    } else {
        const float* bsrc = mat ? bbond : bfeat;
#pragma unroll 16
        for (int m = 0; m < 64; m++) s += bsrc[m] * wrow[m];
        if (!mat) s += bih[j] + bhh[j];
        (mat ? d_FBE : d_FBX)[jp] = s;
    }
}

// ---------------- encoder for W0 ----------------
__global__ void k_encode(const float* __restrict__ in, const float* __restrict__ w,
                         const float* __restrict__ b, float* __restrict__ out, int R) {
    long long tid = (long long)blockIdx.x * blockDim.x + threadIdx.x;
    if (tid >= (long long)R * 64) return;
    int ch = (int)(tid & 63);
    long long r = tid >> 6;
    const float* xr = in + r * 18;
    float acc = b[ch];
#pragma unroll
    for (int j = 0; j < 18; j++) acc += xr[j] * w[j * 64 + ch];
    out[tid] = acc;
}

// ---------------- direct gate table: out[R,256] = in[R,18] @ FW + FB (half out) ------
__global__ void __launch_bounds__(256) k_direct(
        const float* __restrict__ in, const float* __restrict__ FW,
        const float* __restrict__ FB, __half* __restrict__ out, int R) {
    __shared__ float FWs[18 * 256];
    __shared__ float Fbs[256];
    __shared__ float xs[16 * 18];
    int tid = threadIdx.x;
    for (int i = tid; i < 18 * 256; i += 256) FWs[i] = FW[i];
    Fbs[tid] = FB[tid];

    long long stride = (long long)gridDim.x * 16;
    long long base = (long long)blockIdx.x * 16;
    auto ldx = [&](long long b, int i) -> float {
        int row = i / 18, col = i - row * 18;
        long long gr = b + row;
        return (i < 288 && gr < R) ? in[gr * 18 + col] : 0.0f;
    };
    float v0 = ldx(base, tid), v1 = ldx(base, tid + 256);
    __syncthreads();

    for (; base < R; base += stride) {
        xs[tid < 288 ? tid : 0] = tid < 288 ? v0 : xs[0];
        if (tid < 32) xs[tid + 256] = v1;
        __syncthreads();
        long long nb = base + stride;
        v0 = ldx(nb, tid); v1 = ldx(nb, tid + 256);
        float acc[16];
#pragma unroll
        for (int r = 0; r < 16; r++) acc[r] = Fbs[tid];
#pragma unroll
        for (int f = 0; f < 18; f++) {
            float w = FWs[f * 256 + tid];
#pragma unroll
            for (int r = 0; r < 16; r++) acc[r] += w * xs[r * 18 + f];
        }
#pragma unroll
        for (int r = 0; r < 16; r++)
            if (base + r < R) out[(base + r) * 256 + tid] = __float2half(acc[r]);
        __syncthreads();
    }
}

// ---------------- HMMA gate tables (R13-proven): out[R,256] = src[R,64] @ W^T (+bias) --
// HALFIN=0: src = in (float) or blend 0.75*in-0.25*in2.  HALFIN=1: src = inh (half).
template <int HALFIN>
__global__ void __launch_bounds__(256) k_gtabmma(
        const float* __restrict__ in, const float* __restrict__ in2,
        const __half* __restrict__ inh,
        const float* __restrict__ W, const float* __restrict__ bias,
        __half* __restrict__ out, int R) {
    __shared__ __half Asm[32 * 72];
    int tid = threadIdx.x;
    int warp = tid >> 5, lane = tid & 31;
    int g = lane >> 2, t = lane & 3;

    unsigned bf[4][4][2];
#pragma unroll
    for (int kk = 0; kk < 4; kk++)
#pragma unroll
        for (int nt = 0; nt < 4; nt++) {
            int n = warp * 32 + nt * 8 + g;
            int k0 = kk * 16 + 2 * t;
            __half2 b0 = __floats2half2_rn(W[n * 64 + k0], W[n * 64 + k0 + 1]);
            __half2 b1 = __floats2half2_rn(W[n * 64 + k0 + 8], W[n * 64 + k0 + 9]);
            bf[kk][nt][0] = *reinterpret_cast<unsigned*>(&b0);
            bf[kk][nt][1] = *reinterpret_cast<unsigned*>(&b1);
        }
    float bb[4][2];
#pragma unroll
    for (int nt = 0; nt < 4; nt++) {
        int n = warp * 32 + nt * 8 + 2 * t;
        bb[nt][0] = bias ? bias[n] : 0.0f;
        bb[nt][1] = bias ? bias[n + 1] : 0.0f;
    }

    long long stride = (long long)gridDim.x * 32;
    long long base = (long long)blockIdx.x * 32;
    auto ldx = [&](long long b, int i) -> float {
        int row = i >> 6, col = i & 63;
        long long gr = b + row;
        if (gr >= R) return 0.0f;
        if (HALFIN) return __half2float(inh[gr * 64 + col]);
        float v = in[gr * 64 + col];
        if (in2) v = 0.75f * v - 0.25f * in2[gr * 64 + col];
        return v;
    };
    float v[8];
#pragma unroll
    for (int j = 0; j < 8; j++) v[j] = ldx(base, tid + j * 256);

    for (; base < R; base += stride) {
#pragma unroll
        for (int j = 0; j < 8; j++) {
            int i = tid + j * 256;
            Asm[(i >> 6) * 72 + (i & 63)] = __float2half(v[j]);
        }
        __syncthreads();
        long long nb = base + stride;
#pragma unroll
        for (int j = 0; j < 8; j++) v[j] = ldx(nb, tid + j * 256);

        float cacc[2][4][4];
#pragma unroll
        for (int mt = 0; mt < 2; mt++)
#pragma unroll
            for (int nt = 0; nt < 4; nt++) {
                cacc[mt][nt][0] = bb[nt][0]; cacc[mt][nt][1] = bb[nt][1];
                cacc[mt][nt][2] = bb[nt][0]; cacc[mt][nt][3] = bb[nt][1];
            }
#pragma unroll
        for (int mt = 0; mt < 2; mt++)
#pragma unroll
            for (int kk = 0; kk < 4; kk++) {
                unsigned a0 = *reinterpret_cast<const unsigned*>(&Asm[(mt * 16 + g) * 72 + kk * 16 + 2 * t]);
                unsigned a1 = *reinterpret_cast<const unsigned*>(&Asm[(mt * 16 + g + 8) * 72 + kk * 16 + 2 * t]);
                unsigned a2 = *reinterpret_cast<const unsigned*>(&Asm[(mt * 16 + g) * 72 + kk * 16 + 2 * t + 8]);
                unsigned a3 = *reinterpret_cast<const unsigned*>(&Asm[(mt * 16 + g + 8) * 72 + kk * 16 + 2 * t + 8]);
#pragma unroll
                for (int nt = 0; nt < 4; nt++) {
                    asm volatile(
                        "mma.sync.aligned.m16n8k16.row.col.f32.f16.f16.f32 "
                        "{%0,%1,%2,%3}, {%4,%5,%6,%7}, {%8,%9}, {%0,%1,%2,%3};"
                        : "+f"(cacc[mt][nt][0]), "+f"(cacc[mt][nt][1]),
                          "+f"(cacc[mt][nt][2]), "+f"(cacc[mt][nt][3])
                        : "r"(a0), "r"(a1), "r"(a2), "r"(a3),
                          "r"(bf[kk][nt][0]), "r"(bf[kk][nt][1]));
                }
            }
#pragma unroll
        for (int mt = 0; mt < 2; mt++)
#pragma unroll
            for (int nt = 0; nt < 4; nt++) {
                int n = warp * 32 + nt * 8 + 2 * t;
                long long r0 = base + mt * 16 + g;
                long long r1 = r0 + 8;
                if (r0 < R) {
                    __half2 h = __floats2half2_rn(cacc[mt][nt][0], cacc[mt][nt][1]);
                    *reinterpret_cast<__half2*>(&out[r0 * 256 + n]) = h;
                }
                if (r1 < R) {
                    __half2 h = __floats2half2_rn(cacc[mt][nt][2], cacc[mt][nt][3]);
                    *reinterpret_cast<__half2*>(&out[r1 * 256 + n]) = h;
                }
            }
        __syncthreads();
    }
}

// ---------------- per-node step-0 state from (half) gate table ----------------
__global__ void k_h0c0(const __half* __restrict__ gnode, __half* __restrict__ h0,
                       __half* __restrict__ c0) {
    long long gid = (long long)blockIdx.x * blockDim.x + threadIdx.x;
    if (gid >= (long long)NN * 64) return;
    uint2 u = reinterpret_cast<const uint2*>(gnode)[gid];
    __half2 p = *reinterpret_cast<__half2*>(&u.x);
    __half2 q = *reinterpret_cast<__half2*>(&u.y);
    float2 f0 = __half22float2(p), f1 = __half22float2(q);
    float c = fsig(f0.x) * ftanh(f1.x);
    float h = fsig(f1.y) * ftanh(c);
    c0[gid] = __float2half(c);
    h0[gid] = __float2half(h);
}

// ---------------- conv0: pure gather + elementwise LSTM step 1 ----------------
__global__ void k_lstm2(const int* __restrict__ paths, const int* __restrict__ ei,
                        const __half* __restrict__ gnode, const __half* __restrict__ gedge,
                        const __half* __restrict__ r0tab, const __half* __restrict__ c0tab,
                        float* __restrict__ acc, int P) {
    long long gid = (long long)blockIdx.x * blockDim.x + threadIdx.x;
    if (gid >= (long long)P * 64) return;
    int k = (int)(gid & 63);
    long long p = gid >> 6;
    int n0 = paths[p * 2], n1 = paths[p * 2 + 1], e0 = ei[p];
    float4 a = ldh4(gnode, (size_t)n1, k);
    float4 b = ldh4(gedge, (size_t)e0, k);
    float4 r = ldh4(r0tab, (size_t)n0, k);
    float c0 = __half2float(c0tab[(size_t)n0 * 64 + k]);
    float gx = a.x + b.x + r.x, gy = a.y + b.y + r.y;
    float gz = a.z + b.z + r.z, gw = a.w + b.w + r.w;
    float c1 = fsig(gy) * c0 + fsig(gx) * ftanh(gz);
    float h1 = fsig(gw) * ftanh(c1);
    atomicAdd(&acc[(size_t)n1 * 64 + k], h1);
}

// ---------------- conv1 (R10-proven 16-path FFMA form, half gathers) ----------------
#define ACC4(W, C) \
    r0.x += a0.C * W.x; r0.y += a0.C * W.y; r0.z += a0.C * W.z; r0.w += a0.C * W.w; \
    r1.x += a1.C * W.x; r1.y += a1.C * W.y; r1.z += a1.C * W.z; r1.w += a1.C * W.w; \
    r2.x += a2.C * W.x; r2.y += a2.C * W.y; r2.z += a2.C * W.z; r2.w += a2.C * W.w; \
    r3.x += a3.C * W.x; r3.y += a3.C * W.y; r3.z += a3.C * W.z; r3.w += a3.C * W.w;

__global__ void k_lstm3(const int* __restrict__ paths, const int* __restrict__ ei,
                        const __half* __restrict__ gnode, const __half* __restrict__ gedge,
                        const __half* __restrict__ r0tab, const __half* __restrict__ c0tab,
                        float* __restrict__ acc, int P) {
    extern __shared__ float sh[];
    float* whhT = sh;             // [64][256]
    float* hsh = sh + 64 * 256;   // [16][64]
    int tid = threadIdx.x;
    for (int i = tid; i < 64 * 256; i += blockDim.x) whhT[i] = d_WHHT[i];
    __syncthreads();

    int k = tid & 63;
    int lp = tid >> 6;
    const float4* whhT4 = (const float4*)whhT;

    for (long long base = (long long)blockIdx.x * 16; base < P; base += (long long)gridDim.x * 16) {
        long long p[4];
        bool valid[4];
        int n0[4], n1[4], n2[4], e0[4], e1[4];
#pragma unroll
        for (int i = 0; i < 4; i++) {
            p[i] = base + lp + 4 * i;
            valid[i] = p[i] < P;
            long long pi = valid[i] ? p[i] : 0;
            n0[i] = paths[pi * 3]; n1[i] = paths[pi * 3 + 1]; n2[i] = paths[pi * 3 + 2];
            e0[i] = ei[pi * 2]; e1[i] = ei[pi * 2 + 1];
        }
        float4 g1[4];
        float c0v[4];
#pragma unroll
        for (int i = 0; i < 4; i++) {
            float4 a = ldh4(gnode, (size_t)n1[i], k);
            float4 b = ldh4(gedge, (size_t)e0[i], k);
            float4 r = ldh4(r0tab, (size_t)n0[i], k);
            g1[i] = make_float4(a.x + b.x + r.x, a.y + b.y + r.y,
                                a.z + b.z + r.z, a.w + b.w + r.w);
            c0v[i] = __half2float(c0tab[(size_t)n0[i] * 64 + k]);
        }
        float4 r0, r1, r2, r3;
#pragma unroll
        for (int i = 0; i < 4; i++) {
            float4 a = ldh4(gnode, (size_t)n2[i], k);
            float4 b = ldh4(gedge, (size_t)e1[i], k);
            float4 v = make_float4(a.x + b.x, a.y + b.y, a.z + b.z, a.w + b.w);
            if (i == 0) r0 = v; else if (i == 1) r1 = v; else if (i == 2) r2 = v; else r3 = v;
        }
        float c1[4], h1[4];
#pragma unroll
        for (int i = 0; i < 4; i++) {
            float c = fsig(g1[i].y) * c0v[i] + fsig(g1[i].x) * ftanh(g1[i].z);
            c1[i] = c;
            h1[i] = fsig(g1[i].w) * ftanh(c);
        }
        __syncthreads();
#pragma unroll
        for (int i = 0; i < 4; i++) hsh[(lp + 4 * i) * 64 + k] = h1[i];
        __syncthreads();
        const float4* h0r = (const float4*)(hsh + (lp + 0) * 64);
        const float4* h1r = (const float4*)(hsh + (lp + 4) * 64);
        const float4* h2r = (const float4*)(hsh + (lp + 8) * 64);
        const float4* h3r = (const float4*)(hsh + (lp + 12) * 64);
#pragma unroll
        for (int mq = 0; mq < 16; mq++) {
            float4 a0 = h0r[mq], a1 = h1r[mq], a2 = h2r[mq], a3 = h3r[mq];
            {
                float4 w = whhT4[(4 * mq + 0) * 64 + k];
                ACC4(w, x)
            }
            {
                float4 w = whhT4[(4 * mq + 1) * 64 + k];
                ACC4(w, y)
            }
            {
                float4 w = whhT4[(4 * mq + 2) * 64 + k];
                ACC4(w, z)
            }
            {
                float4 w = whhT4[(4 * mq + 3) * 64 + k];
                ACC4(w, w)
            }
        }
#pragma unroll
        for (int i = 0; i < 4; i++) {
            float4 r = (i == 0) ? r0 : (i == 1) ? r1 : (i == 2) ? r2 : r3;
            float c = fsig(r.y) * c1[i] + fsig(r.x) * ftanh(r.z);
            float h = fsig(r.w) * ftanh(c);
            if (valid[i]) atomicAdd(&acc[(size_t)n2[i] * 64 + k], h);
        }
    }
}

// ---------------- BN stats (sum + sumsq per channel) -> outStats ----------------
__global__ void k_stats(const float* __restrict__ x, int R, float* __restrict__ outStats) {
    __shared__ float ssum[256], ssq[256];
    int ch = threadIdx.x & 63;
    int rg = threadIdx.x >> 6;
    float s = 0.0f, sq = 0.0f;
    for (int r = blockIdx.x * 4 + rg; r < R; r += gridDim.x * 4) {
        float v = x[(size_t)r * 64 + ch];
        s += v;
        sq += v * v;
    }
    ssum[threadIdx.x] = s;
    ssq[threadIdx.x] = sq;
    __syncthreads();
    if (threadIdx.x < 64) {
        s = ssum[ch] + ssum[64 + ch] + ssum[128 + ch] + ssum[192 + ch];
        sq = ssq[ch] + ssq[64 + ch] + ssq[128 + ch] + ssq[192 + ch];
        atomicAdd(&outStats[ch], s);
        atomicAdd(&outStats[64 + ch], sq);
    }
}

// ---- fused: out = (relu?)(bn(in; statIn)) @ W + bias; accumulates out stats -> statOut --
__global__ void k_bnmm(const float* __restrict__ in, const float* __restrict__ W,
                       const float* __restrict__ bias, const float* __restrict__ g,
                       const float* __restrict__ bvec, float* __restrict__ out,
                       const float* __restrict__ statIn, float* __restrict__ statOut,
                       int R, int relu) {
    __shared__ float WTs[64 * 64];
    __shared__ float xsn[8 * 64];
    __shared__ float ssum[256], ssq[256];
    int tid = threadIdx.x;
    int c = tid & 63;
    int lp = tid >> 6;
    for (int i = tid; i < 4096; i += 256) {
        int m = i >> 6, cc = i & 63;
        int mg = m >> 2, mj = m & 3;
        WTs[cc * 64 + (((mg ^ (cc & 7)) << 2) | mj)] = W[i];
    }
    __syncthreads();

    const float4* W4 = (const float4*)WTs;
    const float4* x4 = (const float4*)xsn;
    int sw = c & 7;
    int wb = c * 16;
    float invR = 1.0f / (float)R;
    float st_s = 0.0f, st_q = 0.0f;

    for (long long base = (long long)blockIdx.x * 8; base < R; base += (long long)gridDim.x * 8) {
        __syncthreads();
        for (int i = tid; i < 512; i += 256) {
            int row = i >> 6, col = i & 63;
            long long gr = base + row;
            float v = 0.0f;
            if (gr < R) {
                v = in[gr * 64 + col];
                float mean = statIn[col] * invR;
                float var = statIn[64 + col] * invR - mean * mean;
                var = fmaxf(var, 0.0f);
                v = (v - mean) * rsqrtf(var + 1e-5f) * g[col] + bvec[col];
                if (relu) v = fmaxf(v, 0.0f);
            }
            xsn[i] = v;
        }
        __syncthreads();
        float a0 = bias[c], a1 = a0;
#pragma unroll
        for (int mg = 0; mg < 16; mg++) {
            float4 w = W4[wb + (mg ^ sw)];
            float4 x0 = x4[lp * 16 + mg];
            float4 x1 = x4[(lp + 4) * 16 + mg];
            a0 += w.x * x0.x + w.y * x0.y + w.z * x0.z + w.w * x0.w;
            a1 += w.x * x1.x + w.y * x1.y + w.z * x1.z + w.w * x1.w;
        }
        if (base + lp < R) { out[(base + lp) * 64 + c] = a0; st_s += a0; st_q += a0 * a0; }
        if (base + lp + 4 < R) { out[(base + lp + 4) * 64 + c] = a1; st_s += a1; st_q += a1 * a1; }
    }
    __syncthreads();
    ssum[tid] = st_s;
    ssq[tid] = st_q;
    __syncthreads();
    if (tid < 64) {
        float s = ssum[tid] + ssum[64 + tid] + ssum[128 + tid] + ssum[192 + tid];
        float q = ssq[tid] + ssq[64 + tid] + ssq[128 + tid] + ssq[192 + tid];
        atomicAdd(&statOut[tid], s);
        atomicAdd(&statOut[64 + tid], q);
    }
}

// ---------------- BN apply (+optional relu) ----------------
__global__ void k_bnapply(const float* __restrict__ x, float* __restrict__ out,
                          const float* __restrict__ g, const float* __restrict__ b,
                          const float* __restrict__ statIn, int R, int relu) {
    long long i = (long long)blockIdx.x * blockDim.x + threadIdx.x;
    if (i >= (long long)R * 64) return;
    int ch = (int)(i & 63);
    float invR = 1.0f / (float)R;
    float mean = statIn[ch] * invR;
    float var = statIn[64 + ch] * invR - mean * mean;
    var = fmaxf(var, 0.0f);
    float sc = rsqrtf(var + 1e-5f);
    float v = (x[i] - mean) * sc * g[ch] + b[ch];
    if (relu) v = fmaxf(v, 0.0f);
    out[i] = v;
}

// ---- BN apply for W2 + fused attention sums: s1 += W0*W1, s2 += W0*W2 ----------------
__global__ void k_bnapply_att(const float* __restrict__ x, float* __restrict__ out,
                              const float* __restrict__ g, const float* __restrict__ b,
                              const float* __restrict__ statIn) {
    __shared__ float sh1[256], sh2[256];
    int tid = threadIdx.x;
    int ch = tid & 63;
    float invR = 1.0f / (float)NN;
    float mean = statIn[ch] * invR;
    float var = statIn[64 + ch] * invR - mean * mean;
    var = fmaxf(var, 0.0f);
    float sc = rsqrtf(var + 1e-5f) * g[ch];
    float bc = b[ch];
    float s1 = 0.0f, s2 = 0.0f;
    for (long long i = (long long)blockIdx.x * 256 + tid; i < (long long)NN * 64;
         i += (long long)gridDim.x * 256) {
        float v = fmaxf((x[i] - mean) * sc + bc, 0.0f);
        out[i] = v;
        float q = d_W0[i];
        s1 += q * d_W1[i];
        s2 += q * v;
    }
    sh1[tid] = s1;
    sh2[tid] = s2;
    __syncthreads();
    if (tid < 64) {
        s1 = sh1[ch] + sh1[64 + ch] + sh1[128 + ch] + sh1[192 + ch];
        s2 = sh2[ch] + sh2[64 + ch] + sh2[128 + ch] + sh2[192 + ch];
        atomicAdd(&d_S[ch], s1);
        atomicAdd(&d_S[64 + ch], s2);
    }
}

// ---------------- attention scores -> softmax weights ----------------
__global__ void k_attfinal(const float* __restrict__ w_att, const float* __restrict__ b_att) {
    int t = threadIdx.x;  // 32 threads
    float scores[2];
#pragma unroll
    for (int j = 0; j < 2; j++) {
        float v0 = d_S[j * 64 + t], v1 = d_S[j * 64 + 32 + t];
        float mn = fminf(v0, v1), mx = fmaxf(v0, v1);
#pragma unroll
        for (int o = 16; o; o >>= 1) {
            mn = fminf(mn, __shfl_xor_sync(0xffffffffu, mn, o));
            mx = fmaxf(mx, __shfl_xor_sync(0xffffffffu, mx, o));
        }
        float inv = 1.0f / (mx - mn + 1e-6f);
        float d = (v0 - mn) * inv * w_att[t] + (v1 - mn) * inv * w_att[32 + t];
#pragma unroll
        for (int o = 16; o; o >>= 1) d += __shfl_xor_sync(0xffffffffu, d, o);
        scores[j] = d + b_att[0];
    }
    if (t == 0) {
        float m = fmaxf(scores[0], scores[1]);
        float e0 = __expf(scores[0] - m), e1 = __expf(scores[1] - m);
        float inv = 1.0f / (e0 + e1);
        d_S[128] = e0 * inv;
        d_S[129] = e1 * inv;
    }
}

// ---------------- combine + global_add_pool ----------------
__global__ void k_pool(const int* __restrict__ batch) {
    long long i = (long long)blockIdx.x * blockDim.x + threadIdx.x;
    if (i >= (long long)NN * 64) return;
    int n = (int)(i >> 6), ch = (int)(i & 63);
    float a0 = d_S[128], a1 = d_S[129];
    float v = d_W0[i] + a0 * d_W1[i] + a1 * d_W2[i];
    atomicAdd(&d_POOL[(size_t)batch[n] * 64 + ch], v);
}

// ---------------- head ----------------
__global__ void k_head(const float* __restrict__ wl1, const float* __restrict__ bl1,
                       const float* __restrict__ wl2, const float* __restrict__ bl2,
                       float* __restrict__ out) {
    __shared__ float row[64], hid[64];
    int g = blockIdx.x, t = threadIdx.x;  // 64 threads
    row[t] = d_POOL[g * 64 + t];
    __syncthreads();
    float a = bl1[t];
#pragma unroll 16
    for (int m = 0; m < 64; m++) a += row[m] * wl1[m * 64 + t];
    hid[t] = fmaxf(a, 0.0f);
    __syncthreads();
    if (t < NCC) {
        float o = bl2[t];
#pragma unroll 16
        for (int m = 0; m < 64; m++) o += hid[m] * wl2[m * NCC + t];
        out[g * NCC + t] = o;
    }
}

// ---------------- launch ----------------
extern "C" void kernel_launch(void* const* d_in, const int* in_sizes, int n_in,
                              void* d_out, int out_size) {
    const float* x         = (const float*)d_in[0];
    const float* edge_attr = (const float*)d_in[1];
    const int*   paths2    = (const int*)d_in[2];
    const int*   ei2       = (const int*)d_in[3];
    const int*   paths3    = (const int*)d_in[4];
    const int*   ei3       = (const int*)d_in[5];
    const int*   batch     = (const int*)d_in[6];
    const float* w_feat = (const float*)d_in[7];
    const float* b_feat = (const float*)d_in[8];
    const float* w_bond = (const float*)d_in[9];
    const float* b_bond = (const float*)d_in[10];
    const float* w_ih   = (const float*)d_in[11];
    const float* w_hh   = (const float*)d_in[12];
    const float* b_ih   = (const float*)d_in[13];
    const float* b_hh   = (const float*)d_in[14];
    const float* bn_g   = (const float*)d_in[15];
    const float* bn_b   = (const float*)d_in[16];
    const float* mlp_w1 = (const float*)d_in[17];
    const float* mlp_b1 = (const float*)d_in[18];
    const float* bn1_g  = (const float*)d_in[19];
    const float* bn1_b  = (const float*)d_in[20];
    const float* mlp_w2 = (const float*)d_in[21];
    const float* mlp_b2 = (const float*)d_in[22];
    const float* bn2_g  = (const float*)d_in[23];
    const float* bn2_b  = (const float*)d_in[24];
    const float* w_att  = (const float*)d_in[25];
    const float* b_att  = (const float*)d_in[26];
    const float* w_l1   = (const float*)d_in[27];
    const float* b_l1   = (const float*)d_in[28];
    const float* w_l2   = (const float*)d_in[29];
    const float* b_l2   = (const float*)d_in[30];
    float* out = (float*)d_out;

    const int SMEM_LS = 64 * 256 * 4 + 16 * 64 * 4;   // 69632
    cudaFuncSetAttribute(k_lstm3, cudaFuncAttributeMaxDynamicSharedMemorySize, SMEM_LS);

    float *pW0, *pAcc, *pTmp, *pW1, *pW2;
    float *pWxp, *pWhp, *pBiasp, *pStats, *pS, *pPool, *pFwx, *pFbx, *pFwe, *pFbe;
    __half *pGn, *pGe, *pR0, *pC0, *pH0;
    cudaGetSymbolAddress((void**)&pW0, d_W0);
    cudaGetSymbolAddress((void**)&pGn, d_GNODE);
    cudaGetSymbolAddress((void**)&pGe, d_GEDGE);
    cudaGetSymbolAddress((void**)&pR0, d_R0);
    cudaGetSymbolAddress((void**)&pH0, d_H0);
    cudaGetSymbolAddress((void**)&pC0, d_C0);
    cudaGetSymbolAddress((void**)&pAcc, d_ACC);
    cudaGetSymbolAddress((void**)&pTmp, d_TMP);
    cudaGetSymbolAddress((void**)&pW1, d_W1);
    cudaGetSymbolAddress((void**)&pW2, d_W2);
    cudaGetSymbolAddress((void**)&pWxp, d_WXP);
    cudaGetSymbolAddress((void**)&pWhp, d_WHP);
    cudaGetSymbolAddress((void**)&pBiasp, d_BIASP);
    cudaGetSymbolAddress((void**)&pStats, d_STATS);
    cudaGetSymbolAddress((void**)&pS, d_S);
    cudaGetSymbolAddress((void**)&pPool, d_POOL);
    cudaGetSymbolAddress((void**)&pFwx, d_FWX);
    cudaGetSymbolAddress((void**)&pFbx, d_FBX);
    cudaGetSymbolAddress((void**)&pFwe, d_FWE);
    cudaGetSymbolAddress((void**)&pFbe, d_FBE);
    float* pS0 = pStats;
    float* pS1 = pStats + 128;

    const int NE = NN * 64;
    const int GB_N = (NE + 255) / 256;
    const int PERS = 444;  // 148 SM x 3

    // weights / fused encoders / tables
    k_prep<<<64, 256>>>(w_ih, w_hh, b_ih, b_hh);
    k_fuse<<<38, 256>>>(w_feat, b_feat, w_bond, b_bond, w_ih, b_ih, b_hh);
    k_encode<<<GB_N, 256>>>(x, w_feat, b_feat, pW0, NN);
    k_direct<<<PERS, 256>>>(edge_attr, pFwe, pFbe, pGe, EE);
    k_direct<<<PERS, 256>>>(x, pFwx, pFbx, pGn, NN);

    // ---- conv 0 (L=2): no per-path GEMM ----
    k_h0c0<<<GB_N, 256>>>(pGn, pH0, pC0);
    k_gtabmma<1><<<PERS, 256>>>(nullptr, nullptr, pH0, pWhp, nullptr, pR0, NN);
    k_zero<<<GB_N, 256>>>(pAcc, NE);
    k_lstm2<<<(int)(((long long)PP2 * 64 + 255) / 256), 256>>>(paths2, ei2, pGn, pGe, pR0, pC0, pAcc, PP2);
    k_zero<<<1, 256>>>(pStats, 256);
    k_stats<<<512, 256>>>(pAcc, NN, pS0);
    k_bnmm<<<PERS, 256>>>(pAcc, mlp_w1, mlp_b1, bn_g, bn_b, pTmp, pS0, pS1, NN, 0);
    k_zero<<<1, 128>>>(pS0, 128);
    k_bnmm<<<PERS, 256>>>(pTmp, mlp_w2, mlp_b2, bn1_g, bn1_b, pAcc, pS1, pS0, NN, 1);
    k_bnapply<<<GB_N, 256>>>(pAcc, pW1, bn2_g, bn2_b, pS0, NN, 1);

    // ---- conv 1 (L=3): Win blended in gtabmma; FFMA recurrence in lstm3 ----
    k_gtabmma<0><<<PERS, 256>>>(pW0, pW1, nullptr, pWxp, pBiasp, pGn, NN);
    k_h0c0<<<GB_N, 256>>>(pGn, pH0, pC0);
    k_gtabmma<1><<<PERS, 256>>>(nullptr, nullptr, pH0, pWhp, nullptr, pR0, NN);
    k_zero<<<GB_N, 256>>>(pAcc, NE);
    k_lstm3<<<PERS, 256, SMEM_LS>>>(paths3, ei3, pGn, pGe, pR0, pC0, pAcc, PP3);
    k_zero<<<1, 256>>>(pStats, 256);
    k_stats<<<512, 256>>>(pAcc, NN, pS0);
    k_bnmm<<<PERS, 256>>>(pAcc, mlp_w1 + 4096, mlp_b1 + 64, bn_g + 64, bn_b + 64, pTmp, pS0, pS1, NN, 0);
    k_zero<<<1, 128>>>(pS0, 128);
    k_bnmm<<<PERS, 256>>>(pTmp, mlp_w2 + 4096, mlp_b2 + 64, bn1_g + 64, bn1_b + 64, pAcc, pS1, pS0, NN, 1);

    // ---- final bnapply fused with attention sums ----
    k_zero<<<1, 160>>>(pS, 132);
    k_bnapply_att<<<512, 256>>>(pAcc, pW2, bn2_g + 64, bn2_b + 64, pS0);
    k_attfinal<<<1, 32>>>(w_att, b_att);
    k_zero<<<(GG * 64 + 255) / 256, 256>>>(pPool, GG * 64);
    k_pool<<<GB_N, 256>>>(batch);
    k_head<<<GG, 64>>>(w_l1, b_l1, w_l2, b_l2, out);
}

// round 16
// speedup vs baseline: 1.6403x; 1.1805x over previous
#include <cuda_runtime.h>
#include <cuda_fp16.h>
#include <cstdint>
#include <math.h>

#define NN   100000
#define EE   200000
#define PP2  250000
#define PP3  500000
#define GG   2048
#define NCC  10

// ---------------- scratch (device globals; no allocations) ----------------
__device__ float  d_W0[NN * 64];
__device__ __half d_GNODE[(size_t)NN * 256];   // fp16 gate tables
__device__ __half d_GEDGE[(size_t)EE * 256];
__device__ __half d_R0[(size_t)NN * 256];
__device__ __half d_H0[NN * 64];
__device__ __half d_C0[NN * 64];
__device__ float  d_ACC[NN * 64];
__device__ float  d_TMP[NN * 64];
__device__ float  d_W1[NN * 64];
__device__ float  d_W2[NN * 64];
__device__ float  d_WXP[256 * 64];
__device__ float  d_WHP[256 * 64];
__device__ float  d_WHHT[64 * 256];
__device__ float  d_BIASP[256];
__device__ float  d_FWX[18 * 256];
__device__ float  d_FBX[256];
__device__ float  d_FWE[18 * 256];
__device__ float  d_FBE[256];
__device__ float  d_STATS[256];   // S0=[0..127], S1=[128..255]
__device__ float  d_S[132];
__device__ float  d_POOL[GG * 64];

__device__ __forceinline__ float fsig(float x) { return 1.0f / (1.0f + __expf(-x)); }
__device__ __forceinline__ float ftanh(float x) { return 2.0f * fsig(2.0f * x) - 1.0f; }

__device__ __forceinline__ float4 ldh4(const __half* base, size_t row, int k) {
    uint2 u = *reinterpret_cast<const uint2*>(base + row * 256 + 4 * k);
    __half2 p = *reinterpret_cast<__half2*>(&u.x);
    __half2 q = *reinterpret_cast<__half2*>(&u.y);
    float2 f0 = __half22float2(p), f1 = __half22float2(q);
    return make_float4(f0.x, f0.y, f1.x, f1.y);
}

// ---------------- zero ----------------
__global__ void k_zero(float* p, int n) {
    int i = blockIdx.x * blockDim.x + threadIdx.x;
    if (i < n) p[i] = 0.0f;
}

// ---------------- weight permutation ----------------
__global__ void k_prep(const float* __restrict__ wih, const float* __restrict__ whh,
                       const float* __restrict__ bih, const float* __restrict__ bhh) {
    int i = blockIdx.x * blockDim.x + threadIdx.x;
    if (i >= 256 * 64) return;
    int jp = i >> 6, m = i & 63;
    int k = jp >> 2, q = jp & 3;
    int j = q * 64 + k;
    d_WXP[i] = wih[j * 128 + m];
    d_WHP[i] = whh[j * 64 + m];
    d_WHHT[m * 256 + jp] = whh[j * 64 + m];
    if (m == 0) d_BIASP[jp] = bih[j] + bhh[j];
}

// ---------------- fused encoder->gate weights ----------------
__global__ void k_fuse(const float* __restrict__ wfeat, const float* __restrict__ bfeat,
                       const float* __restrict__ wbond, const float* __restrict__ bbond,
                       const float* __restrict__ wih, const float* __restrict__ bih,
                       const float* __restrict__ bhh) {
    int t = blockIdx.x * blockDim.x + threadIdx.x;
    if (t >= 2 * 19 * 256) return;
    int jp = t & 255;
    int f = (t >> 8) % 19;
    int mat = t / (19 * 256);
    int k = jp >> 2, q = jp & 3;
    int j = q * 64 + k;
    const float* wrow = wih + j * 128 + (mat ? 64 : 0);
    float s = 0.0f;
    if (f < 18) {
        const float* src = mat ? wbond : wfeat;
#pragma unroll 16
        for (int m = 0; m < 64; m++) s += src[f * 64 + m] * wrow[m];
        (mat ? d_FWE : d_FWX)[f * 256 + jp] = s;
    } else {
        const float* bsrc = mat ? bbond : bfeat;
#pragma unroll 16
        for (int m = 0; m < 64; m++) s += bsrc[m] * wrow[m];
        if (!mat) s += bih[j] + bhh[j];
        (mat ? d_FBE : d_FBX)[jp] = s;
    }
}

// ---------------- encoder for W0 ----------------
__global__ void k_encode(const float* __restrict__ in, const float* __restrict__ w,
                         const float* __restrict__ b, float* __restrict__ out, int R) {
    long long tid = (long long)blockIdx.x * blockDim.x + threadIdx.x;
    if (tid >= (long long)R * 64) return;
    int ch = (int)(tid & 63);
    long long r = tid >> 6;
    const float* xr = in + r * 18;
    float acc = b[ch];
#pragma unroll
    for (int j = 0; j < 18; j++) acc += xr[j] * w[j * 64 + ch];
    out[tid] = acc;
}

// ---------------- HMMA direct gate table: out[R,256] = in[R,18] @ FW + FB ------------
// K padded 18->32; stationary FW fragments; A fp16 smem tile [32][40].
__global__ void __launch_bounds__(256) k_directmma(
        const float* __restrict__ in, const float* __restrict__ FW,
        const float* __restrict__ FB, __half* __restrict__ out, int R) {
    __shared__ __half Asm[32 * 40];
    int tid = threadIdx.x;
    int warp = tid >> 5, lane = tid & 31;
    int g = lane >> 2, t = lane & 3;

    for (int i = tid; i < 32 * 40; i += 256) Asm[i] = __float2half(0.0f);

    unsigned bf[2][4][2];
#pragma unroll
    for (int kk = 0; kk < 2; kk++)
#pragma unroll
        for (int nt = 0; nt < 4; nt++) {
            int n = warp * 32 + nt * 8 + g;
            int k0 = kk * 16 + 2 * t;
            auto wv = [&](int k) { return (k < 18) ? FW[k * 256 + n] : 0.0f; };
            __half2 b0 = __floats2half2_rn(wv(k0), wv(k0 + 1));
            __half2 b1 = __floats2half2_rn(wv(k0 + 8), wv(k0 + 9));
            bf[kk][nt][0] = *reinterpret_cast<unsigned*>(&b0);
            bf[kk][nt][1] = *reinterpret_cast<unsigned*>(&b1);
        }
    float bb[4][2];
#pragma unroll
    for (int nt = 0; nt < 4; nt++) {
        int n = warp * 32 + nt * 8 + 2 * t;
        bb[nt][0] = FB[n];
        bb[nt][1] = FB[n + 1];
    }

    long long stride = (long long)gridDim.x * 32;
    long long base = (long long)blockIdx.x * 32;
    auto ldx = [&](long long b, int i) -> float {
        int row = i / 18, col = i - row * 18;
        long long gr = b + row;
        return (i < 576 && gr < R) ? in[gr * 18 + col] : 0.0f;
    };
    float v0 = ldx(base, tid), v1 = ldx(base, tid + 256), v2 = ldx(base, tid + 512);
    __syncthreads();

    for (; base < R; base += stride) {
        {
            int i0 = tid, i1 = tid + 256;
            Asm[(i0 / 18) * 40 + (i0 % 18)] = __float2half(v0);
            if (i1 < 576) Asm[(i1 / 18) * 40 + (i1 % 18)] = __float2half(v1);
            int i2 = tid + 512;
            if (i2 < 576) Asm[(i2 / 18) * 40 + (i2 % 18)] = __float2half(v2);
        }
        __syncthreads();
        long long nb = base + stride;
        v0 = ldx(nb, tid); v1 = ldx(nb, tid + 256); v2 = ldx(nb, tid + 512);

        float cacc[2][4][4];
#pragma unroll
        for (int mt = 0; mt < 2; mt++)
#pragma unroll
            for (int nt = 0; nt < 4; nt++) {
                cacc[mt][nt][0] = bb[nt][0]; cacc[mt][nt][1] = bb[nt][1];
                cacc[mt][nt][2] = bb[nt][0]; cacc[mt][nt][3] = bb[nt][1];
            }
#pragma unroll
        for (int mt = 0; mt < 2; mt++)
#pragma unroll
            for (int kk = 0; kk < 2; kk++) {
                unsigned a0 = *reinterpret_cast<const unsigned*>(&Asm[(mt * 16 + g) * 40 + kk * 16 + 2 * t]);
                unsigned a1 = *reinterpret_cast<const unsigned*>(&Asm[(mt * 16 + g + 8) * 40 + kk * 16 + 2 * t]);
                unsigned a2 = *reinterpret_cast<const unsigned*>(&Asm[(mt * 16 + g) * 40 + kk * 16 + 2 * t + 8]);
                unsigned a3 = *reinterpret_cast<const unsigned*>(&Asm[(mt * 16 + g + 8) * 40 + kk * 16 + 2 * t + 8]);
#pragma unroll
                for (int nt = 0; nt < 4; nt++) {
                    asm volatile(
                        "mma.sync.aligned.m16n8k16.row.col.f32.f16.f16.f32 "
                        "{%0,%1,%2,%3}, {%4,%5,%6,%7}, {%8,%9}, {%0,%1,%2,%3};"
                        : "+f"(cacc[mt][nt][0]), "+f"(cacc[mt][nt][1]),
                          "+f"(cacc[mt][nt][2]), "+f"(cacc[mt][nt][3])
                        : "r"(a0), "r"(a1), "r"(a2), "r"(a3),
                          "r"(bf[kk][nt][0]), "r"(bf[kk][nt][1]));
                }
            }
#pragma unroll
        for (int mt = 0; mt < 2; mt++)
#pragma unroll
            for (int nt = 0; nt < 4; nt++) {
                int n = warp * 32 + nt * 8 + 2 * t;
                long long r0 = base + mt * 16 + g;
                long long r1 = r0 + 8;
                if (r0 < R) {
                    __half2 h = __floats2half2_rn(cacc[mt][nt][0], cacc[mt][nt][1]);
                    *reinterpret_cast<__half2*>(&out[r0 * 256 + n]) = h;
                }
                if (r1 < R) {
                    __half2 h = __floats2half2_rn(cacc[mt][nt][2], cacc[mt][nt][3]);
                    *reinterpret_cast<__half2*>(&out[r1 * 256 + n]) = h;
                }
            }
        __syncthreads();
    }
}

// ---------------- HMMA gate tables (R13-proven): out[R,256] = src[R,64] @ W^T (+bias) --
template <int HALFIN>
__global__ void __launch_bounds__(256) k_gtabmma(
        const float* __restrict__ in, const float* __restrict__ in2,
        const __half* __restrict__ inh,
        const float* __restrict__ W, const float* __restrict__ bias,
        __half* __restrict__ out, int R) {
    __shared__ __half Asm[32 * 72];
    int tid = threadIdx.x;
    int warp = tid >> 5, lane = tid & 31;
    int g = lane >> 2, t = lane & 3;

    unsigned bf[4][4][2];
#pragma unroll
    for (int kk = 0; kk < 4; kk++)
#pragma unroll
        for (int nt = 0; nt < 4; nt++) {
            int n = warp * 32 + nt * 8 + g;
            int k0 = kk * 16 + 2 * t;
            __half2 b0 = __floats2half2_rn(W[n * 64 + k0], W[n * 64 + k0 + 1]);
            __half2 b1 = __floats2half2_rn(W[n * 64 + k0 + 8], W[n * 64 + k0 + 9]);
            bf[kk][nt][0] = *reinterpret_cast<unsigned*>(&b0);
            bf[kk][nt][1] = *reinterpret_cast<unsigned*>(&b1);
        }
    float bb[4][2];
#pragma unroll
    for (int nt = 0; nt < 4; nt++) {
        int n = warp * 32 + nt * 8 + 2 * t;
        bb[nt][0] = bias ? bias[n] : 0.0f;
        bb[nt][1] = bias ? bias[n + 1] : 0.0f;
    }

    long long stride = (long long)gridDim.x * 32;
    long long base = (long long)blockIdx.x * 32;
    auto ldx = [&](long long b, int i) -> float {
        int row = i >> 6, col = i & 63;
        long long gr = b + row;
        if (gr >= R) return 0.0f;
        if (HALFIN) return __half2float(inh[gr * 64 + col]);
        float v = in[gr * 64 + col];
        if (in2) v = 0.75f * v - 0.25f * in2[gr * 64 + col];
        return v;
    };
    float v[8];
#pragma unroll
    for (int j = 0; j < 8; j++) v[j] = ldx(base, tid + j * 256);

    for (; base < R; base += stride) {
#pragma unroll
        for (int j = 0; j < 8; j++) {
            int i = tid + j * 256;
            Asm[(i >> 6) * 72 + (i & 63)] = __float2half(v[j]);
        }
        __syncthreads();
        long long nb = base + stride;
#pragma unroll
        for (int j = 0; j < 8; j++) v[j] = ldx(nb, tid + j * 256);

        float cacc[2][4][4];
#pragma unroll
        for (int mt = 0; mt < 2; mt++)
#pragma unroll
            for (int nt = 0; nt < 4; nt++) {
                cacc[mt][nt][0] = bb[nt][0]; cacc[mt][nt][1] = bb[nt][1];
                cacc[mt][nt][2] = bb[nt][0]; cacc[mt][nt][3] = bb[nt][1];
            }
#pragma unroll
        for (int mt = 0; mt < 2; mt++)
#pragma unroll
            for (int kk = 0; kk < 4; kk++) {
                unsigned a0 = *reinterpret_cast<const unsigned*>(&Asm[(mt * 16 + g) * 72 + kk * 16 + 2 * t]);
                unsigned a1 = *reinterpret_cast<const unsigned*>(&Asm[(mt * 16 + g + 8) * 72 + kk * 16 + 2 * t]);
                unsigned a2 = *reinterpret_cast<const unsigned*>(&Asm[(mt * 16 + g) * 72 + kk * 16 + 2 * t + 8]);
                unsigned a3 = *reinterpret_cast<const unsigned*>(&Asm[(mt * 16 + g + 8) * 72 + kk * 16 + 2 * t + 8]);
#pragma unroll
                for (int nt = 0; nt < 4; nt++) {
                    asm volatile(
                        "mma.sync.aligned.m16n8k16.row.col.f32.f16.f16.f32 "
                        "{%0,%1,%2,%3}, {%4,%5,%6,%7}, {%8,%9}, {%0,%1,%2,%3};"
                        : "+f"(cacc[mt][nt][0]), "+f"(cacc[mt][nt][1]),
                          "+f"(cacc[mt][nt][2]), "+f"(cacc[mt][nt][3])
                        : "r"(a0), "r"(a1), "r"(a2), "r"(a3),
                          "r"(bf[kk][nt][0]), "r"(bf[kk][nt][1]));
                }
            }
#pragma unroll
        for (int mt = 0; mt < 2; mt++)
#pragma unroll
            for (int nt = 0; nt < 4; nt++) {
                int n = warp * 32 + nt * 8 + 2 * t;
                long long r0 = base + mt * 16 + g;
                long long r1 = r0 + 8;
                if (r0 < R) {
                    __half2 h = __floats2half2_rn(cacc[mt][nt][0], cacc[mt][nt][1]);
                    *reinterpret_cast<__half2*>(&out[r0 * 256 + n]) = h;
                }
                if (r1 < R) {
                    __half2 h = __floats2half2_rn(cacc[mt][nt][2], cacc[mt][nt][3]);
                    *reinterpret_cast<__half2*>(&out[r1 * 256 + n]) = h;
                }
            }
        __syncthreads();
    }
}

// ---------------- per-node step-0 state from (half) gate table ----------------
__global__ void k_h0c0(const __half* __restrict__ gnode, __half* __restrict__ h0,
                       __half* __restrict__ c0) {
    long long gid = (long long)blockIdx.x * blockDim.x + threadIdx.x;
    if (gid >= (long long)NN * 64) return;
    uint2 u = reinterpret_cast<const uint2*>(gnode)[gid];
    __half2 p = *reinterpret_cast<__half2*>(&u.x);
    __half2 q = *reinterpret_cast<__half2*>(&u.y);
    float2 f0 = __half22float2(p), f1 = __half22float2(q);
    float c = fsig(f0.x) * ftanh(f1.x);
    float h = fsig(f1.y) * ftanh(c);
    c0[gid] = __float2half(c);
    h0[gid] = __float2half(h);
}

// ---------------- conv0: pure gather + elementwise LSTM step 1 ----------------
__global__ void k_lstm2(const int* __restrict__ paths, const int* __restrict__ ei,
                        const __half* __restrict__ gnode, const __half* __restrict__ gedge,
                        const __half* __restrict__ r0tab, const __half* __restrict__ c0tab,
                        float* __restrict__ acc, int P) {
    long long gid = (long long)blockIdx.x * blockDim.x + threadIdx.x;
    if (gid >= (long long)P * 64) return;
    int k = (int)(gid & 63);
    long long p = gid >> 6;
    int n0 = paths[p * 2], n1 = paths[p * 2 + 1], e0 = ei[p];
    float4 a = ldh4(gnode, (size_t)n1, k);
    float4 b = ldh4(gedge, (size_t)e0, k);
    float4 r = ldh4(r0tab, (size_t)n0, k);
    float c0 = __half2float(c0tab[(size_t)n0 * 64 + k]);
    float gx = a.x + b.x + r.x, gy = a.y + b.y + r.y;
    float gz = a.z + b.z + r.z, gw = a.w + b.w + r.w;
    float c1 = fsig(gy) * c0 + fsig(gx) * ftanh(gz);
    float h1 = fsig(gw) * ftanh(c1);
    atomicAdd(&acc[(size_t)n1 * 64 + k], h1);
}

// ---------------- conv1 (R10-proven 16-path FFMA form, half gathers) ----------------
#define ACC4(W, C) \
    r0.x += a0.C * W.x; r0.y += a0.C * W.y; r0.z += a0.C * W.z; r0.w += a0.C * W.w; \
    r1.x += a1.C * W.x; r1.y += a1.C * W.y; r1.z += a1.C * W.z; r1.w += a1.C * W.w; \
    r2.x += a2.C * W.x; r2.y += a2.C * W.y; r2.z += a2.C * W.z; r2.w += a2.C * W.w; \
    r3.x += a3.C * W.x; r3.y += a3.C * W.y; r3.z += a3.C * W.z; r3.w += a3.C * W.w;

__global__ void k_lstm3(const int* __restrict__ paths, const int* __restrict__ ei,
                        const __half* __restrict__ gnode, const __half* __restrict__ gedge,
                        const __half* __restrict__ r0tab, const __half* __restrict__ c0tab,
                        float* __restrict__ acc, int P) {
    extern __shared__ float sh[];
    float* whhT = sh;             // [64][256]
    float* hsh = sh + 64 * 256;   // [16][64]
    int tid = threadIdx.x;
    for (int i = tid; i < 64 * 256; i += blockDim.x) whhT[i] = d_WHHT[i];
    __syncthreads();

    int k = tid & 63;
    int lp = tid >> 6;
    const float4* whhT4 = (const float4*)whhT;

    for (long long base = (long long)blockIdx.x * 16; base < P; base += (long long)gridDim.x * 16) {
        long long p[4];
        bool valid[4];
        int n0[4], n1[4], n2[4], e0[4], e1[4];
#pragma unroll
        for (int i = 0; i < 4; i++) {
            p[i] = base + lp + 4 * i;
            valid[i] = p[i] < P;
            long long pi = valid[i] ? p[i] : 0;
            n0[i] = paths[pi * 3]; n1[i] = paths[pi * 3 + 1]; n2[i] = paths[pi * 3 + 2];
            e0[i] = ei[pi * 2]; e1[i] = ei[pi * 2 + 1];
        }
        float4 g1[4];
        float c0v[4];
#pragma unroll
        for (int i = 0; i < 4; i++) {
            float4 a = ldh4(gnode, (size_t)n1[i], k);
            float4 b = ldh4(gedge, (size_t)e0[i], k);
            float4 r = ldh4(r0tab, (size_t)n0[i], k);
            g1[i] = make_float4(a.x + b.x + r.x, a.y + b.y + r.y,
                                a.z + b.z + r.z, a.w + b.w + r.w);
            c0v[i] = __half2float(c0tab[(size_t)n0[i] * 64 + k]);
        }
        float4 r0, r1, r2, r3;
#pragma unroll
        for (int i = 0; i < 4; i++) {
            float4 a = ldh4(gnode, (size_t)n2[i], k);
            float4 b = ldh4(gedge, (size_t)e1[i], k);
            float4 v = make_float4(a.x + b.x, a.y + b.y, a.z + b.z, a.w + b.w);
            if (i == 0) r0 = v; else if (i == 1) r1 = v; else if (i == 2) r2 = v; else r3 = v;
        }
        float c1[4], h1[4];
#pragma unroll
        for (int i = 0; i < 4; i++) {
            float c = fsig(g1[i].y) * c0v[i] + fsig(g1[i].x) * ftanh(g1[i].z);
            c1[i] = c;
            h1[i] = fsig(g1[i].w) * ftanh(c);
        }
        __syncthreads();
#pragma unroll
        for (int i = 0; i < 4; i++) hsh[(lp + 4 * i) * 64 + k] = h1[i];
        __syncthreads();
        const float4* h0r = (const float4*)(hsh + (lp + 0) * 64);
        const float4* h1r = (const float4*)(hsh + (lp + 4) * 64);
        const float4* h2r = (const float4*)(hsh + (lp + 8) * 64);
        const float4* h3r = (const float4*)(hsh + (lp + 12) * 64);
#pragma unroll
        for (int mq = 0; mq < 16; mq++) {
            float4 a0 = h0r[mq], a1 = h1r[mq], a2 = h2r[mq], a3 = h3r[mq];
            {
                float4 w = whhT4[(4 * mq + 0) * 64 + k];
                ACC4(w, x)
            }
            {
                float4 w = whhT4[(4 * mq + 1) * 64 + k];
                ACC4(w, y)
            }
            {
                float4 w = whhT4[(4 * mq + 2) * 64 + k];
                ACC4(w, z)
            }
            {
                float4 w = whhT4[(4 * mq + 3) * 64 + k];
                ACC4(w, w)
            }
        }
#pragma unroll
        for (int i = 0; i < 4; i++) {
            float4 r = (i == 0) ? r0 : (i == 1) ? r1 : (i == 2) ? r2 : r3;
            float c = fsig(r.y) * c1[i] + fsig(r.x) * ftanh(r.z);
            float h = fsig(r.w) * ftanh(c);
            if (valid[i]) atomicAdd(&acc[(size_t)n2[i] * 64 + k], h);
        }
    }
}

// ---------------- BN stats (sum + sumsq per channel) -> outStats ----------------
__global__ void k_stats(const float* __restrict__ x, int R, float* __restrict__ outStats) {
    __shared__ float ssum[256], ssq[256];
    int ch = threadIdx.x & 63;
    int rg = threadIdx.x >> 6;
    float s = 0.0f, sq = 0.0f;
    for (int r = blockIdx.x * 4 + rg; r < R; r += gridDim.x * 4) {
        float v = x[(size_t)r * 64 + ch];
        s += v;
        sq += v * v;
    }
    ssum[threadIdx.x] = s;
    ssq[threadIdx.x] = sq;
    __syncthreads();
    if (threadIdx.x < 64) {
        s = ssum[ch] + ssum[64 + ch] + ssum[128 + ch] + ssum[192 + ch];
        sq = ssq[ch] + ssq[64 + ch] + ssq[128 + ch] + ssq[192 + ch];
        atomicAdd(&outStats[ch], s);
        atomicAdd(&outStats[64 + ch], sq);
    }
}

// ---- HMMA fused: out = bn(in;statIn)(relu?) @ W[64,64] + bias; stats(out) -> statOut --
__global__ void __launch_bounds__(256) k_bnmmmma(
        const float* __restrict__ in, const float* __restrict__ W,
        const float* __restrict__ bias, const float* __restrict__ gam,
        const float* __restrict__ bvec, float* __restrict__ out,
        const float* __restrict__ statIn, float* __restrict__ statOut,
        int R, int relu) {
    __shared__ __half Asm[32 * 72];
    __shared__ float ssum[64], ssq[64];
    int tid = threadIdx.x;
    int warp = tid >> 5, lane = tid & 31;
    int g = lane >> 2, t = lane & 3;
    if (tid < 64) { ssum[tid] = 0.0f; ssq[tid] = 0.0f; }

    int nB = warp * 8 + g;       // B-frag col
    int nc = warp * 8 + 2 * t;   // D cols (nc, nc+1)

    unsigned bf[4][2];
#pragma unroll
    for (int kk = 0; kk < 4; kk++) {
        int k0 = kk * 16 + 2 * t;
        __half2 b0 = __floats2half2_rn(W[k0 * 64 + nB], W[(k0 + 1) * 64 + nB]);
        __half2 b1 = __floats2half2_rn(W[(k0 + 8) * 64 + nB], W[(k0 + 9) * 64 + nB]);
        bf[kk][0] = *reinterpret_cast<unsigned*>(&b0);
        bf[kk][1] = *reinterpret_cast<unsigned*>(&b1);
    }
    float bias0 = bias[nc], bias1 = bias[nc + 1];

    // loader channel is fixed: col = tid & 63
    int lc = tid & 63;
    float invR = 1.0f / (float)R;
    float mean = statIn[lc] * invR;
    float var = fmaxf(statIn[64 + lc] * invR - mean * mean, 0.0f);
    float lsc = rsqrtf(var + 1e-5f) * gam[lc];
    float lbc = bvec[lc];

    long long stride = (long long)gridDim.x * 32;
    long long base = (long long)blockIdx.x * 32;
    auto ldx = [&](long long b, int j) -> float {
        long long gr = b + (tid >> 6) + j * 4;
        if (gr >= R) return 0.0f;
        float v = (in[gr * 64 + lc] - mean) * lsc + lbc;
        if (relu) v = fmaxf(v, 0.0f);
        return v;
    };
    float v[8];
#pragma unroll
    for (int j = 0; j < 8; j++) v[j] = ldx(base, j);
    __syncthreads();

    float st_s0 = 0.0f, st_q0 = 0.0f, st_s1 = 0.0f, st_q1 = 0.0f;

    for (; base < R; base += stride) {
#pragma unroll
        for (int j = 0; j < 8; j++)
            Asm[((tid >> 6) + j * 4) * 72 + lc] = __float2half(v[j]);
        __syncthreads();
        long long nb = base + stride;
#pragma unroll
        for (int j = 0; j < 8; j++) v[j] = ldx(nb, j);

        float cacc[2][4];
#pragma unroll
        for (int mt = 0; mt < 2; mt++) {
            cacc[mt][0] = bias0; cacc[mt][1] = bias1;
            cacc[mt][2] = bias0; cacc[mt][3] = bias1;
        }
#pragma unroll
        for (int mt = 0; mt < 2; mt++)
#pragma unroll
            for (int kk = 0; kk < 4; kk++) {
                unsigned a0 = *reinterpret_cast<const unsigned*>(&Asm[(mt * 16 + g) * 72 + kk * 16 + 2 * t]);
                unsigned a1 = *reinterpret_cast<const unsigned*>(&Asm[(mt * 16 + g + 8) * 72 + kk * 16 + 2 * t]);
                unsigned a2 = *reinterpret_cast<const unsigned*>(&Asm[(mt * 16 + g) * 72 + kk * 16 + 2 * t + 8]);
                unsigned a3 = *reinterpret_cast<const unsigned*>(&Asm[(mt * 16 + g + 8) * 72 + kk * 16 + 2 * t + 8]);
                asm volatile(
                    "mma.sync.aligned.m16n8k16.row.col.f32.f16.f16.f32 "
                    "{%0,%1,%2,%3}, {%4,%5,%6,%7}, {%8,%9}, {%0,%1,%2,%3};"
                    : "+f"(cacc[mt][0]), "+f"(cacc[mt][1]),
                      "+f"(cacc[mt][2]), "+f"(cacc[mt][3])
                    : "r"(a0), "r"(a1), "r"(a2), "r"(a3),
                      "r"(bf[kk][0]), "r"(bf[kk][1]));
            }
#pragma unroll
        for (int mt = 0; mt < 2; mt++) {
            long long r0 = base + mt * 16 + g;
            long long r1 = r0 + 8;
            if (r0 < R) {
                *reinterpret_cast<float2*>(&out[r0 * 64 + nc]) = make_float2(cacc[mt][0], cacc[mt][1]);
                st_s0 += cacc[mt][0]; st_q0 += cacc[mt][0] * cacc[mt][0];
                st_s1 += cacc[mt][1]; st_q1 += cacc[mt][1] * cacc[mt][1];
            }
            if (r1 < R) {
                *reinterpret_cast<float2*>(&out[r1 * 64 + nc]) = make_float2(cacc[mt][2], cacc[mt][3]);
                st_s0 += cacc[mt][2]; st_q0 += cacc[mt][2] * cacc[mt][2];
                st_s1 += cacc[mt][3]; st_q1 += cacc[mt][3] * cacc[mt][3];
            }
        }
        __syncthreads();
    }
    atomicAdd(&ssum[nc], st_s0);
    atomicAdd(&ssq[nc], st_q0);
    atomicAdd(&ssum[nc + 1], st_s1);
    atomicAdd(&ssq[nc + 1], st_q1);
    __syncthreads();
    if (tid < 64) {
        atomicAdd(&statOut[tid], ssum[tid]);
        atomicAdd(&statOut[64 + tid], ssq[tid]);
    }
}

// ---------------- BN apply (+optional relu) ----------------
__global__ void k_bnapply(const float* __restrict__ x, float* __restrict__ out,
                          const float* __restrict__ g, const float* __restrict__ b,
                          const float* __restrict__ statIn, int R, int relu) {
    long long i = (long long)blockIdx.x * blockDim.x + threadIdx.x;
    if (i >= (long long)R * 64) return;
    int ch = (int)(i & 63);
    float invR = 1.0f / (float)R;
    float mean = statIn[ch] * invR;
    float var = statIn[64 + ch] * invR - mean * mean;
    var = fmaxf(var, 0.0f);
    float sc = rsqrtf(var + 1e-5f);
    float v = (x[i] - mean) * sc * g[ch] + b[ch];
    if (relu) v = fmaxf(v, 0.0f);
    out[i] = v;
}

// ---- BN apply for W2 + fused attention sums: s1 += W0*W1, s2 += W0*W2 ----------------
__global__ void k_bnapply_att(const float* __restrict__ x, float* __restrict__ out,
                              const float* __restrict__ g, const float* __restrict__ b,
                              const float* __restrict__ statIn) {
    __shared__ float sh1[256], sh2[256];
    int tid = threadIdx.x;
    int ch = tid & 63;
    float invR = 1.0f / (float)NN;
    float mean = statIn[ch] * invR;
    float var = statIn[64 + ch] * invR - mean * mean;
    var = fmaxf(var, 0.0f);
    float sc = rsqrtf(var + 1e-5f) * g[ch];
    float bc = b[ch];
    float s1 = 0.0f, s2 = 0.0f;
    for (long long i = (long long)blockIdx.x * 256 + tid; i < (long long)NN * 64;
         i += (long long)gridDim.x * 256) {
        float v = fmaxf((x[i] - mean) * sc + bc, 0.0f);
        out[i] = v;
        float q = d_W0[i];
        s1 += q * d_W1[i];
        s2 += q * v;
    }
    sh1[tid] = s1;
    sh2[tid] = s2;
    __syncthreads();
    if (tid < 64) {
        s1 = sh1[ch] + sh1[64 + ch] + sh1[128 + ch] + sh1[192 + ch];
        s2 = sh2[ch] + sh2[64 + ch] + sh2[128 + ch] + sh2[192 + ch];
        atomicAdd(&d_S[ch], s1);
        atomicAdd(&d_S[64 + ch], s2);
    }
}

// ---------------- attention scores -> softmax weights ----------------
__global__ void k_attfinal(const float* __restrict__ w_att, const float* __restrict__ b_att) {
    int t = threadIdx.x;  // 32 threads
    float scores[2];
#pragma unroll
    for (int j = 0; j < 2; j++) {
        float v0 = d_S[j * 64 + t], v1 = d_S[j * 64 + 32 + t];
        float mn = fminf(v0, v1), mx = fmaxf(v0, v1);
#pragma unroll
        for (int o = 16; o; o >>= 1) {
            mn = fminf(mn, __shfl_xor_sync(0xffffffffu, mn, o));
            mx = fmaxf(mx, __shfl_xor_sync(0xffffffffu, mx, o));
        }
        float inv = 1.0f / (mx - mn + 1e-6f);
        float d = (v0 - mn) * inv * w_att[t] + (v1 - mn) * inv * w_att[32 + t];
#pragma unroll
        for (int o = 16; o; o >>= 1) d += __shfl_xor_sync(0xffffffffu, d, o);
        scores[j] = d + b_att[0];
    }
    if (t == 0) {
        float m = fmaxf(scores[0], scores[1]);
        float e0 = __expf(scores[0] - m), e1 = __expf(scores[1] - m);
        float inv = 1.0f / (e0 + e1);
        d_S[128] = e0 * inv;
        d_S[129] = e1 * inv;
    }
}

// ---------------- combine + global_add_pool ----------------
__global__ void k_pool(const int* __restrict__ batch) {
    long long i = (long long)blockIdx.x * blockDim.x + threadIdx.x;
    if (i >= (long long)NN * 64) return;
    int n = (int)(i >> 6), ch = (int)(i & 63);
    float a0 = d_S[128], a1 = d_S[129];
    float v = d_W0[i] + a0 * d_W1[i] + a1 * d_W2[i];
    atomicAdd(&d_POOL[(size_t)batch[n] * 64 + ch], v);
}

// ---------------- head ----------------
__global__ void k_head(const float* __restrict__ wl1, const float* __restrict__ bl1,
                       const float* __restrict__ wl2, const float* __restrict__ bl2,
                       float* __restrict__ out) {
    __shared__ float row[64], hid[64];
    int g = blockIdx.x, t = threadIdx.x;  // 64 threads
    row[t] = d_POOL[g * 64 + t];
    __syncthreads();
    float a = bl1[t];
#pragma unroll 16
    for (int m = 0; m < 64; m++) a += row[m] * wl1[m * 64 + t];
    hid[t] = fmaxf(a, 0.0f);
    __syncthreads();
    if (t < NCC) {
        float o = bl2[t];
#pragma unroll 16
        for (int m = 0; m < 64; m++) o += hid[m] * wl2[m * NCC + t];
        out[g * NCC + t] = o;
    }
}

// ---------------- launch ----------------
extern "C" void kernel_launch(void* const* d_in, const int* in_sizes, int n_in,
                              void* d_out, int out_size) {
    const float* x         = (const float*)d_in[0];
    const float* edge_attr = (const float*)d_in[1];
    const int*   paths2    = (const int*)d_in[2];
    const int*   ei2       = (const int*)d_in[3];
    const int*   paths3    = (const int*)d_in[4];
    const int*   ei3       = (const int*)d_in[5];
    const int*   batch     = (const int*)d_in[6];
    const float* w_feat = (const float*)d_in[7];
    const float* b_feat = (const float*)d_in[8];
    const float* w_bond = (const float*)d_in[9];
    const float* b_bond = (const float*)d_in[10];
    const float* w_ih   = (const float*)d_in[11];
    const float* w_hh   = (const float*)d_in[12];
    const float* b_ih   = (const float*)d_in[13];
    const float* b_hh   = (const float*)d_in[14];
    const float* bn_g   = (const float*)d_in[15];
    const float* bn_b   = (const float*)d_in[16];
    const float* mlp_w1 = (const float*)d_in[17];
    const float* mlp_b1 = (const float*)d_in[18];
    const float* bn1_g  = (const float*)d_in[19];
    const float* bn1_b  = (const float*)d_in[20];
    const float* mlp_w2 = (const float*)d_in[21];
    const float* mlp_b2 = (const float*)d_in[22];
    const float* bn2_g  = (const float*)d_in[23];
    const float* bn2_b  = (const float*)d_in[24];
    const float* w_att  = (const float*)d_in[25];
    const float* b_att  = (const float*)d_in[26];
    const float* w_l1   = (const float*)d_in[27];
    const float* b_l1   = (const float*)d_in[28];
    const float* w_l2   = (const float*)d_in[29];
    const float* b_l2   = (const float*)d_in[30];
    float* out = (float*)d_out;

    const int SMEM_LS = 64 * 256 * 4 + 16 * 64 * 4;   // 69632
    cudaFuncSetAttribute(k_lstm3, cudaFuncAttributeMaxDynamicSharedMemorySize, SMEM_LS);

    float *pW0, *pAcc, *pTmp, *pW1, *pW2;
    float *pWxp, *pWhp, *pBiasp, *pStats, *pS, *pPool, *pFwx, *pFbx, *pFwe, *pFbe;
    __half *pGn, *pGe, *pR0, *pC0, *pH0;
    cudaGetSymbolAddress((void**)&pW0, d_W0);
    cudaGetSymbolAddress((void**)&pGn, d_GNODE);
    cudaGetSymbolAddress((void**)&pGe, d_GEDGE);
    cudaGetSymbolAddress((void**)&pR0, d_R0);
    cudaGetSymbolAddress((void**)&pH0, d_H0);
    cudaGetSymbolAddress((void**)&pC0, d_C0);
    cudaGetSymbolAddress((void**)&pAcc, d_ACC);
    cudaGetSymbolAddress((void**)&pTmp, d_TMP);
    cudaGetSymbolAddress((void**)&pW1, d_W1);
    cudaGetSymbolAddress((void**)&pW2, d_W2);
    cudaGetSymbolAddress((void**)&pWxp, d_WXP);
    cudaGetSymbolAddress((void**)&pWhp, d_WHP);
    cudaGetSymbolAddress((void**)&pBiasp, d_BIASP);
    cudaGetSymbolAddress((void**)&pStats, d_STATS);
    cudaGetSymbolAddress((void**)&pS, d_S);
    cudaGetSymbolAddress((void**)&pPool, d_POOL);
    cudaGetSymbolAddress((void**)&pFwx, d_FWX);
    cudaGetSymbolAddress((void**)&pFbx, d_FBX);
    cudaGetSymbolAddress((void**)&pFwe, d_FWE);
    cudaGetSymbolAddress((void**)&pFbe, d_FBE);
    float* pS0 = pStats;
    float* pS1 = pStats + 128;

    const int NE = NN * 64;
    const int GB_N = (NE + 255) / 256;
    const int PERS = 444;  // 148 SM x 3

    // weights / fused encoders / tables
    k_prep<<<64, 256>>>(w_ih, w_hh, b_ih, b_hh);
    k_fuse<<<38, 256>>>(w_feat, b_feat, w_bond, b_bond, w_ih, b_ih, b_hh);
    k_encode<<<GB_N, 256>>>(x, w_feat, b_feat, pW0, NN);
    k_directmma<<<PERS, 256>>>(edge_attr, pFwe, pFbe, pGe, EE);
    k_directmma<<<PERS, 256>>>(x, pFwx, pFbx, pGn, NN);

    // ---- conv 0 (L=2): no per-path GEMM ----
    k_h0c0<<<GB_N, 256>>>(pGn, pH0, pC0);
    k_gtabmma<1><<<PERS, 256>>>(nullptr, nullptr, pH0, pWhp, nullptr, pR0, NN);
    k_zero<<<GB_N, 256>>>(pAcc, NE);
    k_lstm2<<<(int)(((long long)PP2 * 64 + 255) / 256), 256>>>(paths2, ei2, pGn, pGe, pR0, pC0, pAcc, PP2);
    k_zero<<<1, 256>>>(pStats, 256);
    k_stats<<<512, 256>>>(pAcc, NN, pS0);
    k_bnmmmma<<<PERS, 256>>>(pAcc, mlp_w1, mlp_b1, bn_g, bn_b, pTmp, pS0, pS1, NN, 0);
    k_zero<<<1, 128>>>(pS0, 128);
    k_bnmmmma<<<PERS, 256>>>(pTmp, mlp_w2, mlp_b2, bn1_g, bn1_b, pAcc, pS1, pS0, NN, 1);
    k_bnapply<<<GB_N, 256>>>(pAcc, pW1, bn2_g, bn2_b, pS0, NN, 1);

    // ---- conv 1 (L=3): Win blended in gtabmma; FFMA recurrence in lstm3 ----
    k_gtabmma<0><<<PERS, 256>>>(pW0, pW1, nullptr, pWxp, pBiasp, pGn, NN);
    k_h0c0<<<GB_N, 256>>>(pGn, pH0, pC0);
    k_gtabmma<1><<<PERS, 256>>>(nullptr, nullptr, pH0, pWhp, nullptr, pR0, NN);
    k_zero<<<GB_N, 256>>>(pAcc, NE);
    k_lstm3<<<PERS, 256, SMEM_LS>>>(paths3, ei3, pGn, pGe, pR0, pC0, pAcc, PP3);
    k_zero<<<1, 256>>>(pStats, 256);
    k_stats<<<512, 256>>>(pAcc, NN, pS0);
    k_bnmmmma<<<PERS, 256>>>(pAcc, mlp_w1 + 4096, mlp_b1 + 64, bn_g + 64, bn_b + 64, pTmp, pS0, pS1, NN, 0);
    k_zero<<<1, 128>>>(pS0, 128);
    k_bnmmmma<<<PERS, 256>>>(pTmp, mlp_w2 + 4096, mlp_b2 + 64, bn1_g + 64, bn1_b + 64, pAcc, pS1, pS0, NN, 1);

    // ---- final bnapply fused with attention sums ----
    k_zero<<<1, 160>>>(pS, 132);
    k_bnapply_att<<<512, 256>>>(pAcc, pW2, bn2_g + 64, bn2_b + 64, pS0);
    k_attfinal<<<1, 32>>>(w_att, b_att);
    k_zero<<<(GG * 64 + 255) / 256, 256>>>(pPool, GG * 64);
    k_pool<<<GB_N, 256>>>(batch);
    k_head<<<GG, 64>>>(w_l1, b_l1, w_l2, b_l2, out);
}